// round 8
// baseline (speedup 1.0000x reference)
#include <cuda_runtime.h>
#include <math.h>

// B=2, C=32, H=512, W=512, SCALE=2 -> Hs=Ws=256, S2=4
// argsort indices are permutations of {0..3} -> 24 distinct per-pixel codes.
// ifft2 linear => per (b,c): ifft2(X) = sum_p Cp[bc][p] * M_p, M_p = ifft2(mask_p).
// Masks real -> pack pairs (2q,2q+1) into 12 complex IFFT planes; M(-u)=conj(M(u))
// lets one thread emit two output pixels. FFTs are radix-4 Stockham.
// kE: q-outer accumulation (16 persistent chains) for low regs / high occupancy;
// 2x2 pool moved into kA as a streaming pass writing `out`, kE does out += mag.

// ---------------- scratch ----------------
__device__ float         d_Fpart[2 * 8 * 8];
__device__ float2        d_Cp[64 * 24];
__device__ unsigned char d_ppix[256 * 256];
__device__ float2        d_Ym[12 * 256 * 256];     // row-IFFT intermediate (6.3MB)
__device__ float2        d_W[12 * 256 * 256];      // packed-pair 2D IFFT (6.3MB)

// ---------------- f32x2 helpers ----------------
__device__ __forceinline__ unsigned long long pk2(float lo, float hi) {
    unsigned long long r;
    asm("mov.b64 %0, {%1, %2};" : "=l"(r) : "f"(lo), "f"(hi));
    return r;
}
__device__ __forceinline__ void upk2(unsigned long long v, float& lo, float& hi) {
    asm("mov.b64 {%0, %1}, %2;" : "=f"(lo), "=f"(hi) : "l"(v));
}
__device__ __forceinline__ unsigned long long ffma2(unsigned long long a,
                                                    unsigned long long b,
                                                    unsigned long long c) {
    unsigned long long r;
    asm("fma.rn.f32x2 %0, %1, %2, %3;" : "=l"(r) : "l"(a), "l"(b), "l"(c));
    return r;
}

__device__ __forceinline__ float2 cmul(float2 w, float2 z) {
    return make_float2(w.x * z.x - w.y * z.y, w.x * z.y + w.y * z.x);
}

// permutation unranking; code packs perm elems at 2-bit fields
__device__ __forceinline__ int perm_code(int p) {
    int avail[4] = {0, 1, 2, 3};
    const int f[3] = {6, 2, 1};
    int code = 0, rem = p;
#pragma unroll
    for (int pos = 0; pos < 3; pos++) {
        int sel = rem / f[pos];
        rem -= sel * f[pos];
        int e = avail[sel];
#pragma unroll
        for (int q = 0; q < 3; q++)
            if (q >= sel) avail[q] = avail[q + 1];
        code |= e << (2 * pos);
    }
    code |= avail[0] << 6;
    return code;
}

// ---------------- KA: fused F-partials + pixel perm ids + 2x2 pool -> out ----------------
__global__ void __launch_bounds__(512) kA(const float* __restrict__ x,
                                          const int* __restrict__ ei,
                                          float* __restrict__ out) {
    int blk = blockIdx.x;
    if (blk < 16) {
        int b = blk >> 3, hb = blk & 7;
        int w = threadIdx.x;  // 512
        const float* xp = x + (size_t)b * 32 * 512 * 512 + (size_t)(hb * 64) * 512 + w;
        float s = 0.f;
#pragma unroll 8
        for (int h = 0; h < 64; h++) s += xp[(size_t)h * 512];

        float vals[8];
#pragma unroll
        for (int t = 0; t < 4; t++) {
            float ph = (float)(t * w) * (1.0f / 256.0f);
            float sn, cs;
            sincospif(ph, &sn, &cs);
            vals[2 * t] = s * cs;
            vals[2 * t + 1] = -s * sn;
        }
        unsigned lane = threadIdx.x & 31, wid = threadIdx.x >> 5;
#pragma unroll
        for (int v = 0; v < 8; v++)
#pragma unroll
            for (int off = 16; off; off >>= 1)
                vals[v] += __shfl_down_sync(0xffffffff, vals[v], off);
        __shared__ float wsum[16][8];
        if (lane == 0)
            for (int v = 0; v < 8; v++) wsum[wid][v] = vals[v];
        __syncthreads();
        if (threadIdx.x == 0) {
            for (int v = 0; v < 8; v++) {
                float a = 0.f;
                for (int k = 0; k < 16; k++) a += wsum[k][v];
                d_Fpart[(b * 8 + hb) * 8 + v] = a;
            }
        }
    } else if (blk < 144) {
        __shared__ unsigned char lut[256];
        if (threadIdx.x < 24) lut[perm_code(threadIdx.x)] = (unsigned char)threadIdx.x;
        __syncthreads();
        int pix = (blk - 16) * 512 + threadIdx.x;
        unsigned code = 0;
#pragma unroll
        for (int P = 0; P < 4; P++)
            code |= ((unsigned)ei[(size_t)P * 2097152 + pix] & 3u) << (2 * P);
        d_ppix[pix] = lut[code];
    } else {
        // pool: 8192 blocks, each 512 threads = 2 output rows of one (b,c)
        int blk2 = blk - 144;        // 0..8191
        int bc = blk2 >> 7;          // 0..63
        int rp = blk2 & 127;         // row pair
        int t = threadIdx.x;
        int row = rp * 2 + (t >> 8);
        int j = t & 255;
        const float* xb = x + (size_t)bc * 262144 + (size_t)(2 * row) * 512 + 2 * j;
        float2 a0 = *(const float2*)xb;
        float2 a1 = *(const float2*)(xb + 512);
        out[(size_t)bc * 65536 + row * 256 + j] =
            0.25f * (a0.x + a0.y + a1.x + a1.y);
    }
}

// ---------------- kB body (runs as the extra block of kC) ----------------
__device__ void kB_body(const float* __restrict__ w1r, const float* __restrict__ b1r,
                        const float* __restrict__ w2r, const float* __restrict__ b2r,
                        const float* __restrict__ w1i, const float* __restrict__ b1i,
                        const float* __restrict__ w2i, const float* __restrict__ b2i) {
    __shared__ float2 sF[8];
    __shared__ float sTR[1024], sTI[1024];
    int tid = threadIdx.x;  // 128
    if (tid < 8) {
        int b = tid >> 2, k = tid & 3;
        float re = 0.f, im = 0.f;
        for (int hb = 0; hb < 8; hb++) {
            re += d_Fpart[(b * 8 + hb) * 8 + 2 * k];
            im += d_Fpart[(b * 8 + hb) * 8 + 2 * k + 1];
        }
        sF[tid] = make_float2(re, im);
    }
    __syncthreads();

    for (int e = tid; e < 2048; e += 128) {
        int isI = e >> 10;
        int r = e & 1023;
        int b = r >> 9;
        int g = (r >> 4) & 31;
        int o = (r >> 2) & 3;
        int k = r & 3;
        const float* w1 = isI ? w1i : w1r;
        const float* b1 = isI ? b1i : b1r;
        const float* w2 = isI ? w2i : w2r;
        const float* b2 = isI ? b2i : b2r;
        float v = isI ? sF[b * 4 + k].y : sF[b * 4 + k].x;
        float h[4];
#pragma unroll
        for (int ii = 0; ii < 4; ii++) {
            const float* wrow = w1 + (g * 4 + ii) * 4;
            float ws = wrow[0] + wrow[1] + wrow[2] + wrow[3];
            float y = v * ws + b1[g * 4 + ii];
            h[ii] = y > 0.f ? y : 0.1f * y;
        }
        float out = b2[g * 4 + o];
#pragma unroll
        for (int ii = 0; ii < 4; ii++) out += w2[(g * 4 + o) * 4 + ii] * h[ii];
        (isI ? sTI : sTR)[r] = out;
    }
    __syncthreads();

    for (int e = tid; e < 1536; e += 128) {
        int bc = e / 24;
        int p = e - bc * 24;
        int b = bc >> 5, Cc = bc & 31;
        int code = perm_code(p);
        int ks[4] = { code & 3, (code >> 2) & 3, (code >> 4) & 3, (code >> 6) & 3 };
        float ar[4], ai[4];
#pragma unroll
        for (int P = 0; P < 4; P++) {
            int g = 8 * P + (Cc >> 2), o = Cc & 3;
            int idx = ((b * 32 + g) * 4 + o) * 4 + ks[P];
            ar[P] = sTR[idx & 1023];
            ai[P] = sTI[idx & 1023];
        }
        float mr = fmaxf(fmaxf(ar[0], ar[1]), fmaxf(ar[2], ar[3]));
        float mi = fmaxf(fmaxf(ai[0], ai[1]), fmaxf(ai[2], ai[3]));
        float er[4], ei_[4], sre = 0.f, sie = 0.f;
#pragma unroll
        for (int P = 0; P < 4; P++) {
            er[P] = __expf(ar[P] - mr); sre += er[P];
            ei_[P] = __expf(ai[P] - mi); sie += ei_[P];
        }
        float rinv = 1.f / sre, iinv = 1.f / sie;
        float Cr = 0.f, Ci = 0.f;
#pragma unroll
        for (int P = 0; P < 4; P++) {
            float sr = er[P] * rinv, si = ei_[P] * iinv;
            float fr = sF[b * 4 + ks[P]].x, fi = sF[b * 4 + ks[P]].y;
            Cr += fr * sr - fi * si;
            Ci += fr * si + fi * sr;
        }
        // fold ifft2 norm 1/65536 and the 1/2 from Hermitian pair reconstruction
        d_Cp[e] = make_float2(Cr * (1.f / 131072.f), Ci * (1.f / 131072.f));
    }
}

// ---------------- KC: pair-packed row IFFT, radix-4 Stockham (2 rows/block) + kB block --------
__global__ void __launch_bounds__(128) kC_row(
        const float* __restrict__ w1r, const float* __restrict__ b1r,
        const float* __restrict__ w2r, const float* __restrict__ b2r,
        const float* __restrict__ w1i, const float* __restrict__ b1i,
        const float* __restrict__ w2i, const float* __restrict__ b2i) {
    if (blockIdx.x == 1536) {
        kB_body(w1r, b1r, w2r, b2r, w1i, b1i, w2i, b2i);
        return;
    }
    __shared__ float2 bufA[2][256], bufB[2][256];
    __shared__ float2 tw[256];
    int q = blockIdx.x >> 7;      // 0..11
    int rp = blockIdx.x & 127;    // row pair
    int t = threadIdx.x;          // 0..127

    for (int n = t; n < 256; n += 128) {
        float sn, cs;
        sincospif((float)n * (1.0f / 128.0f), &sn, &cs);
        tw[n] = make_float2(cs, sn);   // exp(+2*pi*i*n/256)
    }
    int row = t >> 6;
    int tt = t & 63;
    int i = rp * 2 + row;
    int m2q = 2 * q;
#pragma unroll
    for (int r = 0; r < 4; r++) {
        unsigned char id = d_ppix[i * 256 + tt + 64 * r];
        bufA[row][tt + 64 * r] =
            make_float2(id == m2q ? 1.f : 0.f, id == m2q + 1 ? 1.f : 0.f);
    }
    __syncthreads();

    float2 (*A)[256] = bufA;
    float2 (*Bf)[256] = bufB;
#pragma unroll
    for (int s = 0; s < 4; s++) {
        int m = 1 << (2 * s);
        int k = tt & (m - 1);
        int jm = tt - k;          // j*m
        float2 c0 = A[row][tt];
        float2 c1 = A[row][tt + 64];
        float2 c2 = A[row][tt + 128];
        float2 c3 = A[row][tt + 192];
        float2 t0 = make_float2(c0.x + c2.x, c0.y + c2.y);
        float2 t1 = make_float2(c0.x - c2.x, c0.y - c2.y);
        float2 t2 = make_float2(c1.x + c3.x, c1.y + c3.y);
        float2 t3 = make_float2(c1.x - c3.x, c1.y - c3.y);
        float2 z0 = make_float2(t0.x + t2.x, t0.y + t2.y);
        float2 z2 = make_float2(t0.x - t2.x, t0.y - t2.y);
        float2 z1 = make_float2(t1.x - t3.y, t1.y + t3.x);   // t1 + i*t3
        float2 z3 = make_float2(t1.x + t3.y, t1.y - t3.x);   // t1 - i*t3
        int lo = 4 * jm + k;
        Bf[row][lo] = z0;
        Bf[row][lo + m] = cmul(tw[jm], z1);
        Bf[row][lo + 2 * m] = cmul(tw[2 * jm], z2);
        Bf[row][lo + 3 * m] = cmul(tw[3 * jm], z3);
        __syncthreads();
        float2 (*tmp)[256] = A; A = Bf; Bf = tmp;
    }
    size_t base = (size_t)q * 65536 + (size_t)i * 256;
#pragma unroll
    for (int r = 0; r < 4; r++)
        d_Ym[base + tt + 64 * r] = A[row][tt + 64 * r];
}

// ---------------- KD: pair-packed column IFFT, radix-4 Stockham ----------------
__global__ void __launch_bounds__(256) kD_col() {
    __shared__ float2 tA[8 * 257];
    __shared__ float2 tB[8 * 257];
    __shared__ float2 tw[256];
    int q = blockIdx.x >> 5;
    int jt = blockIdx.x & 31;
    int j0 = jt * 8;
    int t = threadIdx.x;  // 256
    {
        float sn, cs;
        sincospif((float)t * (1.0f / 128.0f), &sn, &cs);
        tw[t] = make_float2(cs, sn);
    }
    int c = t & 7;
    int ib = t >> 3;
    size_t ybase = (size_t)q * 65536;

#pragma unroll
    for (int r = 0; r < 8; r++) {
        int i = ib + r * 32;
        tA[c * 257 + i] = d_Ym[ybase + (size_t)i * 256 + j0 + c];
    }
    __syncthreads();

    float2* A = tA;
    float2* Bf = tB;
#pragma unroll
    for (int s = 0; s < 4; s++) {
        int m = 1 << (2 * s);
#pragma unroll
        for (int u = 0; u < 2; u++) {
            int bf = t + u * 256;     // 0..511
            int col = bf >> 6;        // 0..7
            int tt = bf & 63;
            int k = tt & (m - 1);
            int jm = tt - k;
            float2 c0 = A[col * 257 + tt];
            float2 c1 = A[col * 257 + tt + 64];
            float2 c2 = A[col * 257 + tt + 128];
            float2 c3 = A[col * 257 + tt + 192];
            float2 t0 = make_float2(c0.x + c2.x, c0.y + c2.y);
            float2 t1 = make_float2(c0.x - c2.x, c0.y - c2.y);
            float2 t2 = make_float2(c1.x + c3.x, c1.y + c3.y);
            float2 t3 = make_float2(c1.x - c3.x, c1.y - c3.y);
            float2 z0 = make_float2(t0.x + t2.x, t0.y + t2.y);
            float2 z2 = make_float2(t0.x - t2.x, t0.y - t2.y);
            float2 z1 = make_float2(t1.x - t3.y, t1.y + t3.x);
            float2 z3 = make_float2(t1.x + t3.y, t1.y - t3.x);
            int lo = col * 257 + 4 * jm + k;
            Bf[lo] = z0;
            Bf[lo + m] = cmul(tw[jm], z1);
            Bf[lo + 2 * m] = cmul(tw[2 * jm], z2);
            Bf[lo + 3 * m] = cmul(tw[3 * jm], z3);
        }
        __syncthreads();
        float2* tmp = A; A = Bf; Bf = tmp;
    }
#pragma unroll
    for (int r = 0; r < 8; r++) {
        int i = ib + r * 32;
        d_W[ybase + (size_t)i * 256 + j0 + c] = A[c * 257 + i];
    }
}

// ---------------- KE: q-outer combine, 16 persistent chains; out += mag ----------------
__global__ void __launch_bounds__(256, 4) kE_combine(float* __restrict__ out) {
    // sA/sB: [q][k][h] pre-duplicated (v,v) u64, 16B-aligned per (q,k)
    __shared__ unsigned long long sA[12 * 8 * 2];
    __shared__ unsigned long long sB[12 * 8 * 2];
    int i = blockIdx.x;          // 0..128
    int bc0 = blockIdx.y * 8;    // bc chunk base
    int j = threadIdx.x;         // 0..255
    if (threadIdx.x < 192) {
        int k = threadIdx.x / 24, p = threadIdx.x - k * 24;
        float2 cp = d_Cp[(bc0 + k) * 24 + p];
        int q = p >> 1, h = p & 1;
        sA[(q * 8 + k) * 2 + h] = pk2(cp.x, cp.x);
        sB[(q * 8 + k) * 2 + h] = pk2(cp.y, cp.y);
    }
    __syncthreads();

    int im = (256 - i) & 255;
    int jm = (256 - j) & 255;
    int pix = i * 256 + j;
    int mir = im * 256 + jm;

    unsigned long long accA[8], accB[8];
#pragma unroll
    for (int k = 0; k < 8; k++) { accA[k] = 0ull; accB[k] = 0ull; }

#pragma unroll 4
    for (int q = 0; q < 12; q++) {
        float2 w = d_W[(size_t)q * 65536 + pix];
        float2 wp = d_W[(size_t)q * 65536 + mir];
        // U[2q] = (Wr+Wpr, Wi-Wpi); U[2q+1] = (Wi+Wpi, Wpr-Wr)
        unsigned long long U0 = pk2(w.x + wp.x, w.y - wp.y);
        unsigned long long U1 = pk2(w.y + wp.y, wp.x - w.x);
#pragma unroll
        for (int k = 0; k < 8; k++) {
            ulonglong2 a = *(const ulonglong2*)&sA[(q * 8 + k) * 2];
            ulonglong2 b = *(const ulonglong2*)&sB[(q * 8 + k) * 2];
            accA[k] = ffma2(a.x, U0, accA[k]);
            accA[k] = ffma2(a.y, U1, accA[k]);
            accB[k] = ffma2(b.x, U0, accB[k]);
            accB[k] = ffma2(b.y, U1, accB[k]);
        }
    }

    bool doMir = (im != i);   // rows 0 and 128 are self-mirror: skip dup add
#pragma unroll
    for (int k = 0; k < 8; k++) {
        float sa0, sa1, sb0, sb1;
        upk2(accA[k], sa0, sa1);
        upk2(accB[k], sb0, sb1);
        // pixel (i,j):   val = (sa0 - sb1) + i(sa1 + sb0)
        // pixel (-i,-j): val' = (sa0 + sb1) + i(sb0 - sa1)
        float ar = sa0 - sb1, ai = sa1 + sb0;
        float ar2 = sa0 + sb1, ai2 = sb0 - sa1;
        float r2a = fmaxf(fmaf(ar, ar, ai * ai), 1e-38f);
        float r2b = fmaxf(fmaf(ar2, ar2, ai2 * ai2), 1e-38f);
        float mag = r2a * __frsqrt_rn(r2a);
        float mag2 = r2b * __frsqrt_rn(r2b);
        size_t ob = (size_t)(bc0 + k) * 65536;
        out[ob + pix] += mag;
        if (doMir) out[ob + mir] += mag2;
    }
}

// ---------------- launch ----------------
extern "C" void kernel_launch(void* const* d_in, const int* in_sizes, int n_in,
                              void* d_out, int out_size) {
    const float* x   = (const float*)d_in[0];
    const int*   ei  = (const int*)d_in[1];
    const float* w1r = (const float*)d_in[2];
    const float* b1r = (const float*)d_in[3];
    const float* w2r = (const float*)d_in[4];
    const float* b2r = (const float*)d_in[5];
    const float* w1i = (const float*)d_in[6];
    const float* b1i = (const float*)d_in[7];
    const float* w2i = (const float*)d_in[8];
    const float* b2i = (const float*)d_in[9];
    float* out = (float*)d_out;

    kA<<<8336, 512>>>(x, ei, out);
    kC_row<<<1537, 128>>>(w1r, b1r, w2r, b2r, w1i, b1i, w2i, b2i);
    kD_col<<<384, 256>>>();
    kE_combine<<<dim3(129, 8), 256>>>(out);
}

// round 9
// speedup vs baseline: 1.3131x; 1.3131x over previous
#include <cuda_runtime.h>
#include <math.h>

// B=2, C=32, H=512, W=512, SCALE=2 -> Hs=Ws=256, S2=4
// argsort indices are permutations of {0..3} -> 24 distinct per-pixel codes.
// ifft2 linear => per (b,c): ifft2(X) = sum_p Cp[bc][p] * M_p, M_p = ifft2(mask_p).
// Masks real -> pack pairs (2q,2q+1) into 12 complex IFFT planes; M(-u)=conj(M(u))
// lets one thread emit two output pixels. FFTs are radix-4 Stockham.
// kE: q-outer accumulation, 4-bc chunks (low regs -> 5 blocks/SM), pool fused,
// direct store (no RMW).

// ---------------- scratch ----------------
__device__ float         d_Fpart[2 * 8 * 8];
__device__ float2        d_Cp[64 * 24];
__device__ unsigned char d_ppix[256 * 256];
__device__ float2        d_Ym[12 * 256 * 256];     // row-IFFT intermediate (6.3MB)
__device__ float2        d_W[12 * 256 * 256];      // packed-pair 2D IFFT (6.3MB)

// ---------------- f32x2 helpers ----------------
__device__ __forceinline__ unsigned long long pk2(float lo, float hi) {
    unsigned long long r;
    asm("mov.b64 %0, {%1, %2};" : "=l"(r) : "f"(lo), "f"(hi));
    return r;
}
__device__ __forceinline__ void upk2(unsigned long long v, float& lo, float& hi) {
    asm("mov.b64 {%0, %1}, %2;" : "=f"(lo), "=f"(hi) : "l"(v));
}
__device__ __forceinline__ unsigned long long ffma2(unsigned long long a,
                                                    unsigned long long b,
                                                    unsigned long long c) {
    unsigned long long r;
    asm("fma.rn.f32x2 %0, %1, %2, %3;" : "=l"(r) : "l"(a), "l"(b), "l"(c));
    return r;
}

__device__ __forceinline__ float2 cmul(float2 w, float2 z) {
    return make_float2(w.x * z.x - w.y * z.y, w.x * z.y + w.y * z.x);
}

// permutation unranking; code packs perm elems at 2-bit fields
__device__ __forceinline__ int perm_code(int p) {
    int avail[4] = {0, 1, 2, 3};
    const int f[3] = {6, 2, 1};
    int code = 0, rem = p;
#pragma unroll
    for (int pos = 0; pos < 3; pos++) {
        int sel = rem / f[pos];
        rem -= sel * f[pos];
        int e = avail[sel];
#pragma unroll
        for (int q = 0; q < 3; q++)
            if (q >= sel) avail[q] = avail[q + 1];
        code |= e << (2 * pos);
    }
    code |= avail[0] << 6;
    return code;
}

// ---------------- KA: fused F-partials + pixel perm ids ----------------
__global__ void __launch_bounds__(512) kA(const float* __restrict__ x,
                                          const int* __restrict__ ei) {
    int blk = blockIdx.x;
    if (blk < 16) {
        int b = blk >> 3, hb = blk & 7;
        int w = threadIdx.x;  // 512
        const float* xp = x + (size_t)b * 32 * 512 * 512 + (size_t)(hb * 64) * 512 + w;
        float s = 0.f;
#pragma unroll 8
        for (int h = 0; h < 64; h++) s += xp[(size_t)h * 512];

        float vals[8];
#pragma unroll
        for (int t = 0; t < 4; t++) {
            float ph = (float)(t * w) * (1.0f / 256.0f);
            float sn, cs;
            sincospif(ph, &sn, &cs);
            vals[2 * t] = s * cs;
            vals[2 * t + 1] = -s * sn;
        }
        unsigned lane = threadIdx.x & 31, wid = threadIdx.x >> 5;
#pragma unroll
        for (int v = 0; v < 8; v++)
#pragma unroll
            for (int off = 16; off; off >>= 1)
                vals[v] += __shfl_down_sync(0xffffffff, vals[v], off);
        __shared__ float wsum[16][8];
        if (lane == 0)
            for (int v = 0; v < 8; v++) wsum[wid][v] = vals[v];
        __syncthreads();
        if (threadIdx.x == 0) {
            for (int v = 0; v < 8; v++) {
                float a = 0.f;
                for (int k = 0; k < 16; k++) a += wsum[k][v];
                d_Fpart[(b * 8 + hb) * 8 + v] = a;
            }
        }
    } else {
        __shared__ unsigned char lut[256];
        if (threadIdx.x < 24) lut[perm_code(threadIdx.x)] = (unsigned char)threadIdx.x;
        __syncthreads();
        int pix = (blk - 16) * 512 + threadIdx.x;
        unsigned code = 0;
#pragma unroll
        for (int P = 0; P < 4; P++)
            code |= ((unsigned)ei[(size_t)P * 2097152 + pix] & 3u) << (2 * P);
        d_ppix[pix] = lut[code];
    }
}

// ---------------- kB body (runs as the extra block of kC) ----------------
__device__ void kB_body(const float* __restrict__ w1r, const float* __restrict__ b1r,
                        const float* __restrict__ w2r, const float* __restrict__ b2r,
                        const float* __restrict__ w1i, const float* __restrict__ b1i,
                        const float* __restrict__ w2i, const float* __restrict__ b2i) {
    __shared__ float2 sF[8];
    __shared__ float sTR[1024], sTI[1024];
    int tid = threadIdx.x;  // 128
    if (tid < 8) {
        int b = tid >> 2, k = tid & 3;
        float re = 0.f, im = 0.f;
        for (int hb = 0; hb < 8; hb++) {
            re += d_Fpart[(b * 8 + hb) * 8 + 2 * k];
            im += d_Fpart[(b * 8 + hb) * 8 + 2 * k + 1];
        }
        sF[tid] = make_float2(re, im);
    }
    __syncthreads();

    for (int e = tid; e < 2048; e += 128) {
        int isI = e >> 10;
        int r = e & 1023;
        int b = r >> 9;
        int g = (r >> 4) & 31;
        int o = (r >> 2) & 3;
        int k = r & 3;
        const float* w1 = isI ? w1i : w1r;
        const float* b1 = isI ? b1i : b1r;
        const float* w2 = isI ? w2i : w2r;
        const float* b2 = isI ? b2i : b2r;
        float v = isI ? sF[b * 4 + k].y : sF[b * 4 + k].x;
        float h[4];
#pragma unroll
        for (int ii = 0; ii < 4; ii++) {
            const float* wrow = w1 + (g * 4 + ii) * 4;
            float ws = wrow[0] + wrow[1] + wrow[2] + wrow[3];
            float y = v * ws + b1[g * 4 + ii];
            h[ii] = y > 0.f ? y : 0.1f * y;
        }
        float out = b2[g * 4 + o];
#pragma unroll
        for (int ii = 0; ii < 4; ii++) out += w2[(g * 4 + o) * 4 + ii] * h[ii];
        (isI ? sTI : sTR)[r] = out;
    }
    __syncthreads();

    for (int e = tid; e < 1536; e += 128) {
        int bc = e / 24;
        int p = e - bc * 24;
        int b = bc >> 5, Cc = bc & 31;
        int code = perm_code(p);
        int ks[4] = { code & 3, (code >> 2) & 3, (code >> 4) & 3, (code >> 6) & 3 };
        float ar[4], ai[4];
#pragma unroll
        for (int P = 0; P < 4; P++) {
            int g = 8 * P + (Cc >> 2), o = Cc & 3;
            int idx = ((b * 32 + g) * 4 + o) * 4 + ks[P];
            ar[P] = sTR[idx & 1023];
            ai[P] = sTI[idx & 1023];
        }
        float mr = fmaxf(fmaxf(ar[0], ar[1]), fmaxf(ar[2], ar[3]));
        float mi = fmaxf(fmaxf(ai[0], ai[1]), fmaxf(ai[2], ai[3]));
        float er[4], ei_[4], sre = 0.f, sie = 0.f;
#pragma unroll
        for (int P = 0; P < 4; P++) {
            er[P] = __expf(ar[P] - mr); sre += er[P];
            ei_[P] = __expf(ai[P] - mi); sie += ei_[P];
        }
        float rinv = 1.f / sre, iinv = 1.f / sie;
        float Cr = 0.f, Ci = 0.f;
#pragma unroll
        for (int P = 0; P < 4; P++) {
            float sr = er[P] * rinv, si = ei_[P] * iinv;
            float fr = sF[b * 4 + ks[P]].x, fi = sF[b * 4 + ks[P]].y;
            Cr += fr * sr - fi * si;
            Ci += fr * si + fi * sr;
        }
        // fold ifft2 norm 1/65536 and the 1/2 from Hermitian pair reconstruction
        d_Cp[e] = make_float2(Cr * (1.f / 131072.f), Ci * (1.f / 131072.f));
    }
}

// ---------------- KC: pair-packed row IFFT, radix-4 Stockham (2 rows/block) + kB block --------
__global__ void __launch_bounds__(128) kC_row(
        const float* __restrict__ w1r, const float* __restrict__ b1r,
        const float* __restrict__ w2r, const float* __restrict__ b2r,
        const float* __restrict__ w1i, const float* __restrict__ b1i,
        const float* __restrict__ w2i, const float* __restrict__ b2i) {
    if (blockIdx.x == 1536) {
        kB_body(w1r, b1r, w2r, b2r, w1i, b1i, w2i, b2i);
        return;
    }
    __shared__ float2 bufA[2][256], bufB[2][256];
    __shared__ float2 tw[256];
    int q = blockIdx.x >> 7;      // 0..11
    int rp = blockIdx.x & 127;    // row pair
    int t = threadIdx.x;          // 0..127

    for (int n = t; n < 256; n += 128) {
        float sn, cs;
        sincospif((float)n * (1.0f / 128.0f), &sn, &cs);
        tw[n] = make_float2(cs, sn);   // exp(+2*pi*i*n/256)
    }
    int row = t >> 6;
    int tt = t & 63;
    int i = rp * 2 + row;
    int m2q = 2 * q;
#pragma unroll
    for (int r = 0; r < 4; r++) {
        unsigned char id = d_ppix[i * 256 + tt + 64 * r];
        bufA[row][tt + 64 * r] =
            make_float2(id == m2q ? 1.f : 0.f, id == m2q + 1 ? 1.f : 0.f);
    }
    __syncthreads();

    float2 (*A)[256] = bufA;
    float2 (*Bf)[256] = bufB;
#pragma unroll
    for (int s = 0; s < 4; s++) {
        int m = 1 << (2 * s);
        int k = tt & (m - 1);
        int jm = tt - k;          // j*m
        float2 c0 = A[row][tt];
        float2 c1 = A[row][tt + 64];
        float2 c2 = A[row][tt + 128];
        float2 c3 = A[row][tt + 192];
        float2 t0 = make_float2(c0.x + c2.x, c0.y + c2.y);
        float2 t1 = make_float2(c0.x - c2.x, c0.y - c2.y);
        float2 t2 = make_float2(c1.x + c3.x, c1.y + c3.y);
        float2 t3 = make_float2(c1.x - c3.x, c1.y - c3.y);
        float2 z0 = make_float2(t0.x + t2.x, t0.y + t2.y);
        float2 z2 = make_float2(t0.x - t2.x, t0.y - t2.y);
        float2 z1 = make_float2(t1.x - t3.y, t1.y + t3.x);   // t1 + i*t3
        float2 z3 = make_float2(t1.x + t3.y, t1.y - t3.x);   // t1 - i*t3
        int lo = 4 * jm + k;
        Bf[row][lo] = z0;
        Bf[row][lo + m] = cmul(tw[jm], z1);
        Bf[row][lo + 2 * m] = cmul(tw[2 * jm], z2);
        Bf[row][lo + 3 * m] = cmul(tw[3 * jm], z3);
        __syncthreads();
        float2 (*tmp)[256] = A; A = Bf; Bf = tmp;
    }
    size_t base = (size_t)q * 65536 + (size_t)i * 256;
#pragma unroll
    for (int r = 0; r < 4; r++)
        d_Ym[base + tt + 64 * r] = A[row][tt + 64 * r];
}

// ---------------- KD: pair-packed column IFFT, radix-4 Stockham ----------------
__global__ void __launch_bounds__(256) kD_col() {
    __shared__ float2 tA[8 * 257];
    __shared__ float2 tB[8 * 257];
    __shared__ float2 tw[256];
    int q = blockIdx.x >> 5;
    int jt = blockIdx.x & 31;
    int j0 = jt * 8;
    int t = threadIdx.x;  // 256
    {
        float sn, cs;
        sincospif((float)t * (1.0f / 128.0f), &sn, &cs);
        tw[t] = make_float2(cs, sn);
    }
    int c = t & 7;
    int ib = t >> 3;
    size_t ybase = (size_t)q * 65536;

#pragma unroll
    for (int r = 0; r < 8; r++) {
        int i = ib + r * 32;
        tA[c * 257 + i] = d_Ym[ybase + (size_t)i * 256 + j0 + c];
    }
    __syncthreads();

    float2* A = tA;
    float2* Bf = tB;
#pragma unroll
    for (int s = 0; s < 4; s++) {
        int m = 1 << (2 * s);
#pragma unroll
        for (int u = 0; u < 2; u++) {
            int bf = t + u * 256;     // 0..511
            int col = bf >> 6;        // 0..7
            int tt = bf & 63;
            int k = tt & (m - 1);
            int jm = tt - k;
            float2 c0 = A[col * 257 + tt];
            float2 c1 = A[col * 257 + tt + 64];
            float2 c2 = A[col * 257 + tt + 128];
            float2 c3 = A[col * 257 + tt + 192];
            float2 t0 = make_float2(c0.x + c2.x, c0.y + c2.y);
            float2 t1 = make_float2(c0.x - c2.x, c0.y - c2.y);
            float2 t2 = make_float2(c1.x + c3.x, c1.y + c3.y);
            float2 t3 = make_float2(c1.x - c3.x, c1.y - c3.y);
            float2 z0 = make_float2(t0.x + t2.x, t0.y + t2.y);
            float2 z2 = make_float2(t0.x - t2.x, t0.y - t2.y);
            float2 z1 = make_float2(t1.x - t3.y, t1.y + t3.x);
            float2 z3 = make_float2(t1.x + t3.y, t1.y - t3.x);
            int lo = col * 257 + 4 * jm + k;
            Bf[lo] = z0;
            Bf[lo + m] = cmul(tw[jm], z1);
            Bf[lo + 2 * m] = cmul(tw[2 * jm], z2);
            Bf[lo + 3 * m] = cmul(tw[3 * jm], z3);
        }
        __syncthreads();
        float2* tmp = A; A = Bf; Bf = tmp;
    }
#pragma unroll
    for (int r = 0; r < 8; r++) {
        int i = ib + r * 32;
        d_W[ybase + (size_t)i * 256 + j0 + c] = A[c * 257 + i];
    }
}

// ---------------- KE: q-outer combine over 4-bc chunk; pool fused; direct store --------
__global__ void __launch_bounds__(256, 4) kE_combine(const float* __restrict__ x,
                                                     float* __restrict__ out) {
    // sA/sB: [q][k][h] pre-duplicated (v,v) u64, 16B-aligned per (q,k)
    __shared__ unsigned long long sA[12 * 4 * 2];
    __shared__ unsigned long long sB[12 * 4 * 2];
    int i = blockIdx.x;          // 0..128
    int bc0 = blockIdx.y * 4;    // bc chunk base
    int j = threadIdx.x;         // 0..255
    if (threadIdx.x < 96) {
        int k = threadIdx.x / 24, p = threadIdx.x - k * 24;
        float2 cp = d_Cp[(bc0 + k) * 24 + p];
        int q = p >> 1, h = p & 1;
        sA[(q * 4 + k) * 2 + h] = pk2(cp.x, cp.x);
        sB[(q * 4 + k) * 2 + h] = pk2(cp.y, cp.y);
    }
    __syncthreads();

    int im = (256 - i) & 255;
    int jmm = (256 - j) & 255;
    int pix = i * 256 + j;
    int mir = im * 256 + jmm;

    unsigned long long accA[4], accB[4];
#pragma unroll
    for (int k = 0; k < 4; k++) { accA[k] = 0ull; accB[k] = 0ull; }

#pragma unroll
    for (int q = 0; q < 12; q++) {
        float2 w = d_W[q * 65536 + pix];
        float2 wp = d_W[q * 65536 + mir];
        // U[2q] = (Wr+Wpr, Wi-Wpi); U[2q+1] = (Wi+Wpi, Wpr-Wr)
        unsigned long long U0 = pk2(w.x + wp.x, w.y - wp.y);
        unsigned long long U1 = pk2(w.y + wp.y, wp.x - w.x);
#pragma unroll
        for (int k = 0; k < 4; k++) {
            ulonglong2 a = *(const ulonglong2*)&sA[(q * 4 + k) * 2];
            ulonglong2 b = *(const ulonglong2*)&sB[(q * 4 + k) * 2];
            accA[k] = ffma2(a.x, U0, accA[k]);
            accA[k] = ffma2(a.y, U1, accA[k]);
            accB[k] = ffma2(b.x, U0, accB[k]);
            accB[k] = ffma2(b.y, U1, accB[k]);
        }
    }

    // pool offsets (32-bit: max index < 2^24 per channel)
    int xr0 = (2 * i) * 512 + 2 * j;
    int xr1 = xr0 + 512;
    int xm0 = (2 * im) * 512 + 2 * jmm;
    int xm1 = xm0 + 512;

#pragma unroll
    for (int k = 0; k < 4; k++) {
        float sa0, sa1, sb0, sb1;
        upk2(accA[k], sa0, sa1);
        upk2(accB[k], sb0, sb1);
        // pixel (i,j):   val = (sa0 - sb1) + i(sa1 + sb0)
        // pixel (-i,-j): val' = (sa0 + sb1) + i(sb0 - sa1)
        float ar = sa0 - sb1, ai = sa1 + sb0;
        float ar2 = sa0 + sb1, ai2 = sb0 - sa1;
        float r2a = fmaxf(fmaf(ar, ar, ai * ai), 1e-38f);
        float r2b = fmaxf(fmaf(ar2, ar2, ai2 * ai2), 1e-38f);
        float mag = r2a * __frsqrt_rn(r2a);
        float mag2 = r2b * __frsqrt_rn(r2b);

        int bc = bc0 + k;
        const float* xb = x + bc * 262144;
        float2 p0 = *(const float2*)(xb + xr0);
        float2 p1 = *(const float2*)(xb + xr1);
        float2 q0 = *(const float2*)(xb + xm0);
        float2 q1 = *(const float2*)(xb + xm1);
        unsigned ob = (unsigned)bc * 65536u;
        out[ob + pix] = mag + 0.25f * (p0.x + p0.y + p1.x + p1.y);
        out[ob + mir] = mag2 + 0.25f * (q0.x + q0.y + q1.x + q1.y);
    }
}

// ---------------- launch ----------------
extern "C" void kernel_launch(void* const* d_in, const int* in_sizes, int n_in,
                              void* d_out, int out_size) {
    const float* x   = (const float*)d_in[0];
    const int*   ei  = (const int*)d_in[1];
    const float* w1r = (const float*)d_in[2];
    const float* b1r = (const float*)d_in[3];
    const float* w2r = (const float*)d_in[4];
    const float* b2r = (const float*)d_in[5];
    const float* w1i = (const float*)d_in[6];
    const float* b1i = (const float*)d_in[7];
    const float* w2i = (const float*)d_in[8];
    const float* b2i = (const float*)d_in[9];
    float* out = (float*)d_out;

    kA<<<144, 512>>>(x, ei);
    kC_row<<<1537, 128>>>(w1r, b1r, w2r, b2r, w1i, b1i, w2i, b2i);
    kD_col<<<384, 256>>>();
    kE_combine<<<dim3(129, 16), 256>>>(x, out);
}

// round 10
// speedup vs baseline: 2.1607x; 1.6455x over previous
#include <cuda_runtime.h>
#include <math.h>

// B=2, C=32, H=512, W=512, SCALE=2 -> Hs=Ws=256, S2=4
// The 4 patch magnitudes at pixel (i,j) are hypot(A_hb, B_wb) with
//   A0=256-i, A1=i+1, B0=256-j, B1=j+1   (patch p: hb=p&1, wb=p>>1)
// Exact algebra: argsort order depends only on (i>>7, j>>7) and either
// sign(i-j) (diagonal quadrants) or sign(i+j-255) (off-diagonal), stable
// ties landing on the >=/<= branch. Only 8 permutations occur ("regions").
// ifft2 linear => per (b,c): ifft2(X) = sum_r Cp[bc][r] * M_r over 8 region
// masks; masks real -> pack pairs into 4 complex IFFT planes; M(-u)=conj(M(u)).

// ---------------- scratch ----------------
__device__ float  d_Fpart[2 * 8 * 8];
__device__ float2 d_Cp[64 * 8];              // combined coef per (bc, region)
__device__ float2 d_Ym[4 * 256 * 256];       // row-IFFT intermediate (2.1MB)
__device__ float2 d_W[4 * 256 * 256];        // packed-pair 2D IFFT (2.1MB)

// ---------------- f32x2 helpers ----------------
__device__ __forceinline__ unsigned long long pk2(float lo, float hi) {
    unsigned long long r;
    asm("mov.b64 %0, {%1, %2};" : "=l"(r) : "f"(lo), "f"(hi));
    return r;
}
__device__ __forceinline__ void upk2(unsigned long long v, float& lo, float& hi) {
    asm("mov.b64 {%0, %1}, %2;" : "=f"(lo), "=f"(hi) : "l"(v));
}
__device__ __forceinline__ unsigned long long ffma2(unsigned long long a,
                                                    unsigned long long b,
                                                    unsigned long long c) {
    unsigned long long r;
    asm("fma.rn.f32x2 %0, %1, %2, %3;" : "=l"(r) : "l"(a), "l"(b), "l"(c));
    return r;
}
__device__ __forceinline__ float2 cmul(float2 w, float2 z) {
    return make_float2(w.x * z.x - w.y * z.y, w.x * z.y + w.y * z.x);
}

// region id 0..7 for pixel (i,j)
__device__ __forceinline__ int region_id(int i, int j) {
    int qi = i >> 7, qj = j >> 7;
    int u = (qi == qj) ? (i >= j) : (i + j <= 255);
    return (qi << 2) | (qj << 1) | u;
}

// ---------------- KA: column partial sums for F[b,t] (channel 0) ----------------
__global__ void __launch_bounds__(512) kA(const float* __restrict__ x) {
    int b = blockIdx.x >> 3, hb = blockIdx.x & 7;
    int w = threadIdx.x;  // 512
    const float* xp = x + (size_t)b * 32 * 512 * 512 + (size_t)(hb * 64) * 512 + w;
    float s = 0.f;
#pragma unroll 8
    for (int h = 0; h < 64; h++) s += xp[(size_t)h * 512];

    float vals[8];
#pragma unroll
    for (int t = 0; t < 4; t++) {
        float ph = (float)(t * w) * (1.0f / 256.0f);
        float sn, cs;
        sincospif(ph, &sn, &cs);
        vals[2 * t] = s * cs;
        vals[2 * t + 1] = -s * sn;
    }
    unsigned lane = threadIdx.x & 31, wid = threadIdx.x >> 5;
#pragma unroll
    for (int v = 0; v < 8; v++)
#pragma unroll
        for (int off = 16; off; off >>= 1)
            vals[v] += __shfl_down_sync(0xffffffff, vals[v], off);
    __shared__ float wsum[16][8];
    if (lane == 0)
        for (int v = 0; v < 8; v++) wsum[wid][v] = vals[v];
    __syncthreads();
    if (threadIdx.x == 0) {
        for (int v = 0; v < 8; v++) {
            float a = 0.f;
            for (int k = 0; k < 16; k++) a += wsum[k][v];
            d_Fpart[(b * 8 + hb) * 8 + v] = a;
        }
    }
}

// ---------------- kB body (runs as the extra block of kC) ----------------
__device__ void kB_body(const float* __restrict__ w1r, const float* __restrict__ b1r,
                        const float* __restrict__ w2r, const float* __restrict__ b2r,
                        const float* __restrict__ w1i, const float* __restrict__ b1i,
                        const float* __restrict__ w2i, const float* __restrict__ b2i) {
    __shared__ float2 sF[8];
    __shared__ float sTR[1024], sTI[1024];
    int tid = threadIdx.x;  // 128
    if (tid < 8) {
        int b = tid >> 2, k = tid & 3;
        float re = 0.f, im = 0.f;
        for (int hb = 0; hb < 8; hb++) {
            re += d_Fpart[(b * 8 + hb) * 8 + 2 * k];
            im += d_Fpart[(b * 8 + hb) * 8 + 2 * k + 1];
        }
        sF[tid] = make_float2(re, im);
    }
    __syncthreads();

    for (int e = tid; e < 2048; e += 128) {
        int isI = e >> 10;
        int r = e & 1023;
        int b = r >> 9;
        int g = (r >> 4) & 31;
        int o = (r >> 2) & 3;
        int k = r & 3;
        const float* w1 = isI ? w1i : w1r;
        const float* b1 = isI ? b1i : b1r;
        const float* w2 = isI ? w2i : w2r;
        const float* b2 = isI ? b2i : b2r;
        float v = isI ? sF[b * 4 + k].y : sF[b * 4 + k].x;
        float h[4];
#pragma unroll
        for (int ii = 0; ii < 4; ii++) {
            const float* wrow = w1 + (g * 4 + ii) * 4;
            float ws = wrow[0] + wrow[1] + wrow[2] + wrow[3];
            float y = v * ws + b1[g * 4 + ii];
            h[ii] = y > 0.f ? y : 0.1f * y;
        }
        float out = b2[g * 4 + o];
#pragma unroll
        for (int ii = 0; ii < 4; ii++) out += w2[(g * 4 + o) * 4 + ii] * h[ii];
        (isI ? sTI : sTR)[r] = out;
    }
    __syncthreads();

    // 512 outputs: e = bc*8 + region
    for (int e = tid; e < 512; e += 128) {
        int bc = e >> 3;
        int rg = e & 7;
        int b = bc >> 5, Cc = bc & 31;
        // decode region -> descending patch order ks[0..3]
        int qi = (rg >> 2) & 1, qj = (rg >> 1) & 1, u = rg & 1;
        int first = (qj << 1) | qi;
        int last = first ^ 3;
        int mids0 = (qi == qj) ? (u ? 1 : 2) : (u ? 0 : 3);
        int mids1 = mids0 ^ 3;
        int ks[4] = { first, mids0, mids1, last };

        float ar[4], ai[4];
#pragma unroll
        for (int P = 0; P < 4; P++) {
            int g = 8 * P + (Cc >> 2), o = Cc & 3;
            int idx = ((b * 32 + g) * 4 + o) * 4 + ks[P];
            ar[P] = sTR[idx & 1023];
            ai[P] = sTI[idx & 1023];
        }
        float mr = fmaxf(fmaxf(ar[0], ar[1]), fmaxf(ar[2], ar[3]));
        float mi = fmaxf(fmaxf(ai[0], ai[1]), fmaxf(ai[2], ai[3]));
        float er[4], ei_[4], sre = 0.f, sie = 0.f;
#pragma unroll
        for (int P = 0; P < 4; P++) {
            er[P] = __expf(ar[P] - mr); sre += er[P];
            ei_[P] = __expf(ai[P] - mi); sie += ei_[P];
        }
        float rinv = 1.f / sre, iinv = 1.f / sie;
        float Cr = 0.f, Ci = 0.f;
#pragma unroll
        for (int P = 0; P < 4; P++) {
            float sr = er[P] * rinv, si = ei_[P] * iinv;
            float fr = sF[b * 4 + ks[P]].x, fi = sF[b * 4 + ks[P]].y;
            Cr += fr * sr - fi * si;
            Ci += fr * si + fi * sr;
        }
        // fold ifft2 norm 1/65536 and the 1/2 from Hermitian pair reconstruction
        d_Cp[e] = make_float2(Cr * (1.f / 131072.f), Ci * (1.f / 131072.f));
    }
}

// ---------------- KC: pair-packed row IFFT over 4 planes (radix-4) + kB block ------
__global__ void __launch_bounds__(128) kC_row(
        const float* __restrict__ w1r, const float* __restrict__ b1r,
        const float* __restrict__ w2r, const float* __restrict__ b2r,
        const float* __restrict__ w1i, const float* __restrict__ b1i,
        const float* __restrict__ w2i, const float* __restrict__ b2i) {
    if (blockIdx.x == 512) {
        kB_body(w1r, b1r, w2r, b2r, w1i, b1i, w2i, b2i);
        return;
    }
    __shared__ float2 bufA[2][256], bufB[2][256];
    __shared__ float2 tw[256];
    int q = blockIdx.x >> 7;      // 0..3 (plane: regions 2q, 2q+1)
    int rp = blockIdx.x & 127;    // row pair
    int t = threadIdx.x;          // 0..127

    for (int n = t; n < 256; n += 128) {
        float sn, cs;
        sincospif((float)n * (1.0f / 128.0f), &sn, &cs);
        tw[n] = make_float2(cs, sn);   // exp(+2*pi*i*n/256)
    }
    int row = t >> 6;
    int tt = t & 63;
    int i = rp * 2 + row;
    int m2q = 2 * q;
#pragma unroll
    for (int r = 0; r < 4; r++) {
        int col = tt + 64 * r;
        int id = region_id(i, col);
        bufA[row][col] = make_float2(id == m2q ? 1.f : 0.f, id == m2q + 1 ? 1.f : 0.f);
    }
    __syncthreads();

    float2 (*A)[256] = bufA;
    float2 (*Bf)[256] = bufB;
#pragma unroll
    for (int s = 0; s < 4; s++) {
        int m = 1 << (2 * s);
        int k = tt & (m - 1);
        int jm = tt - k;          // j*m
        float2 c0 = A[row][tt];
        float2 c1 = A[row][tt + 64];
        float2 c2 = A[row][tt + 128];
        float2 c3 = A[row][tt + 192];
        float2 t0 = make_float2(c0.x + c2.x, c0.y + c2.y);
        float2 t1 = make_float2(c0.x - c2.x, c0.y - c2.y);
        float2 t2 = make_float2(c1.x + c3.x, c1.y + c3.y);
        float2 t3 = make_float2(c1.x - c3.x, c1.y - c3.y);
        float2 z0 = make_float2(t0.x + t2.x, t0.y + t2.y);
        float2 z2 = make_float2(t0.x - t2.x, t0.y - t2.y);
        float2 z1 = make_float2(t1.x - t3.y, t1.y + t3.x);   // t1 + i*t3
        float2 z3 = make_float2(t1.x + t3.y, t1.y - t3.x);   // t1 - i*t3
        int lo = 4 * jm + k;
        Bf[row][lo] = z0;
        Bf[row][lo + m] = cmul(tw[jm], z1);
        Bf[row][lo + 2 * m] = cmul(tw[2 * jm], z2);
        Bf[row][lo + 3 * m] = cmul(tw[3 * jm], z3);
        __syncthreads();
        float2 (*tmp)[256] = A; A = Bf; Bf = tmp;
    }
    int base = q * 65536 + i * 256;
#pragma unroll
    for (int r = 0; r < 4; r++)
        d_Ym[base + tt + 64 * r] = A[row][tt + 64 * r];
}

// ---------------- KD: pair-packed column IFFT over 4 planes (radix-4) ----------------
__global__ void __launch_bounds__(256) kD_col() {
    __shared__ float2 tA[8 * 257];
    __shared__ float2 tB[8 * 257];
    __shared__ float2 tw[256];
    int q = blockIdx.x >> 5;     // 0..3
    int jt = blockIdx.x & 31;
    int j0 = jt * 8;
    int t = threadIdx.x;  // 256
    {
        float sn, cs;
        sincospif((float)t * (1.0f / 128.0f), &sn, &cs);
        tw[t] = make_float2(cs, sn);
    }
    int c = t & 7;
    int ib = t >> 3;
    int ybase = q * 65536;

#pragma unroll
    for (int r = 0; r < 8; r++) {
        int i = ib + r * 32;
        tA[c * 257 + i] = d_Ym[ybase + i * 256 + j0 + c];
    }
    __syncthreads();

    float2* A = tA;
    float2* Bf = tB;
#pragma unroll
    for (int s = 0; s < 4; s++) {
        int m = 1 << (2 * s);
#pragma unroll
        for (int u = 0; u < 2; u++) {
            int bf = t + u * 256;     // 0..511
            int col = bf >> 6;        // 0..7
            int tt = bf & 63;
            int k = tt & (m - 1);
            int jm = tt - k;
            float2 c0 = A[col * 257 + tt];
            float2 c1 = A[col * 257 + tt + 64];
            float2 c2 = A[col * 257 + tt + 128];
            float2 c3 = A[col * 257 + tt + 192];
            float2 t0 = make_float2(c0.x + c2.x, c0.y + c2.y);
            float2 t1 = make_float2(c0.x - c2.x, c0.y - c2.y);
            float2 t2 = make_float2(c1.x + c3.x, c1.y + c3.y);
            float2 t3 = make_float2(c1.x - c3.x, c1.y - c3.y);
            float2 z0 = make_float2(t0.x + t2.x, t0.y + t2.y);
            float2 z2 = make_float2(t0.x - t2.x, t0.y - t2.y);
            float2 z1 = make_float2(t1.x - t3.y, t1.y + t3.x);
            float2 z3 = make_float2(t1.x + t3.y, t1.y - t3.x);
            int lo = col * 257 + 4 * jm + k;
            Bf[lo] = z0;
            Bf[lo + m] = cmul(tw[jm], z1);
            Bf[lo + 2 * m] = cmul(tw[2 * jm], z2);
            Bf[lo + 3 * m] = cmul(tw[3 * jm], z3);
        }
        __syncthreads();
        float2* tmp = A; A = Bf; Bf = tmp;
    }
#pragma unroll
    for (int r = 0; r < 8; r++) {
        int i = ib + r * 32;
        d_W[ybase + i * 256 + j0 + c] = A[c * 257 + i];
    }
}

// ---------------- KE: q-outer combine over 4-bc chunk; pool fused; direct store --------
__global__ void __launch_bounds__(256, 4) kE_combine(const float* __restrict__ x,
                                                     float* __restrict__ out) {
    // sA/sB: [q][k][h] pre-duplicated (v,v) u64
    __shared__ unsigned long long sA[4 * 4 * 2];
    __shared__ unsigned long long sB[4 * 4 * 2];
    int i = blockIdx.x;          // 0..128
    int bc0 = blockIdx.y * 4;    // bc chunk base
    int j = threadIdx.x;         // 0..255
    if (threadIdx.x < 32) {
        int k = threadIdx.x >> 3, p = threadIdx.x & 7;
        float2 cp = d_Cp[(bc0 + k) * 8 + p];
        int q = p >> 1, h = p & 1;
        sA[(q * 4 + k) * 2 + h] = pk2(cp.x, cp.x);
        sB[(q * 4 + k) * 2 + h] = pk2(cp.y, cp.y);
    }
    __syncthreads();

    int im = (256 - i) & 255;
    int jmm = (256 - j) & 255;
    int pix = i * 256 + j;
    int mir = im * 256 + jmm;

    unsigned long long accA[4], accB[4];
#pragma unroll
    for (int k = 0; k < 4; k++) { accA[k] = 0ull; accB[k] = 0ull; }

#pragma unroll
    for (int q = 0; q < 4; q++) {
        float2 w = d_W[q * 65536 + pix];
        float2 wp = d_W[q * 65536 + mir];
        // U[2q] = (Wr+Wpr, Wi-Wpi); U[2q+1] = (Wi+Wpi, Wpr-Wr)
        unsigned long long U0 = pk2(w.x + wp.x, w.y - wp.y);
        unsigned long long U1 = pk2(w.y + wp.y, wp.x - w.x);
#pragma unroll
        for (int k = 0; k < 4; k++) {
            ulonglong2 a = *(const ulonglong2*)&sA[(q * 4 + k) * 2];
            ulonglong2 b = *(const ulonglong2*)&sB[(q * 4 + k) * 2];
            accA[k] = ffma2(a.x, U0, accA[k]);
            accA[k] = ffma2(a.y, U1, accA[k]);
            accB[k] = ffma2(b.x, U0, accB[k]);
            accB[k] = ffma2(b.y, U1, accB[k]);
        }
    }

    int xr0 = (2 * i) * 512 + 2 * j;
    int xr1 = xr0 + 512;
    int xm0 = (2 * im) * 512 + 2 * jmm;
    int xm1 = xm0 + 512;

#pragma unroll
    for (int k = 0; k < 4; k++) {
        float sa0, sa1, sb0, sb1;
        upk2(accA[k], sa0, sa1);
        upk2(accB[k], sb0, sb1);
        // pixel (i,j):   val = (sa0 - sb1) + i(sa1 + sb0)
        // pixel (-i,-j): val' = (sa0 + sb1) + i(sb0 - sa1)
        float ar = sa0 - sb1, ai = sa1 + sb0;
        float ar2 = sa0 + sb1, ai2 = sb0 - sa1;
        float r2a = fmaxf(fmaf(ar, ar, ai * ai), 1e-38f);
        float r2b = fmaxf(fmaf(ar2, ar2, ai2 * ai2), 1e-38f);
        float mag = r2a * __frsqrt_rn(r2a);
        float mag2 = r2b * __frsqrt_rn(r2b);

        int bc = bc0 + k;
        const float* xb = x + bc * 262144;
        float2 p0 = *(const float2*)(xb + xr0);
        float2 p1 = *(const float2*)(xb + xr1);
        float2 q0 = *(const float2*)(xb + xm0);
        float2 q1 = *(const float2*)(xb + xm1);
        unsigned ob = (unsigned)bc * 65536u;
        out[ob + pix] = mag + 0.25f * (p0.x + p0.y + p1.x + p1.y);
        out[ob + mir] = mag2 + 0.25f * (q0.x + q0.y + q1.x + q1.y);
    }
}

// ---------------- launch ----------------
extern "C" void kernel_launch(void* const* d_in, const int* in_sizes, int n_in,
                              void* d_out, int out_size) {
    const float* x   = (const float*)d_in[0];
    const float* w1r = (const float*)d_in[2];
    const float* b1r = (const float*)d_in[3];
    const float* w2r = (const float*)d_in[4];
    const float* b2r = (const float*)d_in[5];
    const float* w1i = (const float*)d_in[6];
    const float* b1i = (const float*)d_in[7];
    const float* w2i = (const float*)d_in[8];
    const float* b2i = (const float*)d_in[9];
    float* out = (float*)d_out;

    kA<<<16, 512>>>(x);
    kC_row<<<513, 128>>>(w1r, b1r, w2r, b2r, w1i, b1i, w2i, b2i);
    kD_col<<<128, 256>>>();
    kE_combine<<<dim3(129, 16), 256>>>(x, out);
}

// round 11
// speedup vs baseline: 2.2934x; 1.0614x over previous
#include <cuda_runtime.h>
#include <math.h>

// B=2, C=32, H=512, W=512, SCALE=2 -> Hs=Ws=256, S2=4
// The 4 patch magnitudes at pixel (i,j) are hypot(A_hb, B_wb) with
//   A0=256-i, A1=i+1, B0=256-j, B1=j+1   (patch p: hb=p&1, wb=p>>1)
// argsort order depends only on (i>>7, j>>7) and sign(i-j) / sign(i+j-255):
// only 8 permutations ("regions") occur. ifft2 linear => per (b,c):
// ifft2(X) = sum_r Cp[bc][r] * M_r over 8 region masks; masks real -> pack
// pairs into 4 complex IFFT planes; M(-u)=conj(M(u)) gives 2 pixels/thread.

// ---------------- scratch ----------------
__device__ float  d_Fpart[2 * 8 * 8];
__device__ float2 d_Cp[64 * 8];              // combined coef per (bc, region)
__device__ float2 d_Ym[4 * 256 * 256];       // row-IFFT intermediate (2.1MB)
__device__ float2 d_W[4 * 256 * 256];        // packed-pair 2D IFFT (2.1MB)

// ---------------- f32x2 helpers ----------------
__device__ __forceinline__ unsigned long long pk2(float lo, float hi) {
    unsigned long long r;
    asm("mov.b64 %0, {%1, %2};" : "=l"(r) : "f"(lo), "f"(hi));
    return r;
}
__device__ __forceinline__ void upk2(unsigned long long v, float& lo, float& hi) {
    asm("mov.b64 {%0, %1}, %2;" : "=f"(lo), "=f"(hi) : "l"(v));
}
__device__ __forceinline__ unsigned long long ffma2(unsigned long long a,
                                                    unsigned long long b,
                                                    unsigned long long c) {
    unsigned long long r;
    asm("fma.rn.f32x2 %0, %1, %2, %3;" : "=l"(r) : "l"(a), "l"(b), "l"(c));
    return r;
}
__device__ __forceinline__ float2 cmul(float2 w, float2 z) {
    return make_float2(w.x * z.x - w.y * z.y, w.x * z.y + w.y * z.x);
}

// region id 0..7 for pixel (i,j)
__device__ __forceinline__ int region_id(int i, int j) {
    int qi = i >> 7, qj = j >> 7;
    int u = (qi == qj) ? (i >= j) : (i + j <= 255);
    return (qi << 2) | (qj << 1) | u;
}

// ---------------- KA: column partial sums for F[b,t] (channel 0) ----------------
__global__ void __launch_bounds__(512) kA(const float* __restrict__ x) {
    int b = blockIdx.x >> 3, hb = blockIdx.x & 7;
    int w = threadIdx.x;  // 512
    const float* xp = x + (size_t)b * 32 * 512 * 512 + (size_t)(hb * 64) * 512 + w;
    float s = 0.f;
#pragma unroll 8
    for (int h = 0; h < 64; h++) s += xp[(size_t)h * 512];

    float vals[8];
#pragma unroll
    for (int t = 0; t < 4; t++) {
        float ph = (float)(t * w) * (1.0f / 256.0f);
        float sn, cs;
        sincospif(ph, &sn, &cs);
        vals[2 * t] = s * cs;
        vals[2 * t + 1] = -s * sn;
    }
    unsigned lane = threadIdx.x & 31, wid = threadIdx.x >> 5;
#pragma unroll
    for (int v = 0; v < 8; v++)
#pragma unroll
        for (int off = 16; off; off >>= 1)
            vals[v] += __shfl_down_sync(0xffffffff, vals[v], off);
    __shared__ float wsum[16][8];
    if (lane == 0)
        for (int v = 0; v < 8; v++) wsum[wid][v] = vals[v];
    __syncthreads();
    if (threadIdx.x == 0) {
        for (int v = 0; v < 8; v++) {
            float a = 0.f;
            for (int k = 0; k < 16; k++) a += wsum[k][v];
            d_Fpart[(b * 8 + hb) * 8 + v] = a;
        }
    }
}

// ---------------- kB body (runs as the extra block of kD; 256 threads) ----------------
__device__ void kB_body(const float* __restrict__ w1r, const float* __restrict__ b1r,
                        const float* __restrict__ w2r, const float* __restrict__ b2r,
                        const float* __restrict__ w1i, const float* __restrict__ b1i,
                        const float* __restrict__ w2i, const float* __restrict__ b2i) {
    __shared__ float2 sF[8];
    __shared__ float sTR[1024], sTI[1024];
    int tid = threadIdx.x;  // 256
    if (tid < 8) {
        int b = tid >> 2, k = tid & 3;
        float re = 0.f, im = 0.f;
        for (int hb = 0; hb < 8; hb++) {
            re += d_Fpart[(b * 8 + hb) * 8 + 2 * k];
            im += d_Fpart[(b * 8 + hb) * 8 + 2 * k + 1];
        }
        sF[tid] = make_float2(re, im);
    }
    __syncthreads();

#pragma unroll
    for (int e0 = 0; e0 < 2048; e0 += 256) {
        int e = e0 + tid;
        int isI = e >> 10;
        int r = e & 1023;
        int b = r >> 9;
        int g = (r >> 4) & 31;
        int o = (r >> 2) & 3;
        int k = r & 3;
        const float* w1 = isI ? w1i : w1r;
        const float* b1 = isI ? b1i : b1r;
        const float* w2 = isI ? w2i : w2r;
        const float* b2 = isI ? b2i : b2r;
        float v = isI ? sF[b * 4 + k].y : sF[b * 4 + k].x;
        float h[4];
#pragma unroll
        for (int ii = 0; ii < 4; ii++) {
            const float* wrow = w1 + (g * 4 + ii) * 4;
            float ws = wrow[0] + wrow[1] + wrow[2] + wrow[3];
            float y = v * ws + b1[g * 4 + ii];
            h[ii] = y > 0.f ? y : 0.1f * y;
        }
        float out = b2[g * 4 + o];
#pragma unroll
        for (int ii = 0; ii < 4; ii++) out += w2[(g * 4 + o) * 4 + ii] * h[ii];
        (isI ? sTI : sTR)[r] = out;
    }
    __syncthreads();

    // 512 outputs: e = bc*8 + region
    for (int e = tid; e < 512; e += 256) {
        int bc = e >> 3;
        int rg = e & 7;
        int b = bc >> 5, Cc = bc & 31;
        // decode region -> descending patch order ks[0..3]
        int qi = (rg >> 2) & 1, qj = (rg >> 1) & 1, u = rg & 1;
        int first = (qj << 1) | qi;
        int last = first ^ 3;
        int mids0 = (qi == qj) ? (u ? 1 : 2) : (u ? 0 : 3);
        int mids1 = mids0 ^ 3;
        int ks[4] = { first, mids0, mids1, last };

        float ar[4], ai[4];
#pragma unroll
        for (int P = 0; P < 4; P++) {
            int g = 8 * P + (Cc >> 2), o = Cc & 3;
            int idx = ((b * 32 + g) * 4 + o) * 4 + ks[P];
            ar[P] = sTR[idx & 1023];
            ai[P] = sTI[idx & 1023];
        }
        float mr = fmaxf(fmaxf(ar[0], ar[1]), fmaxf(ar[2], ar[3]));
        float mi = fmaxf(fmaxf(ai[0], ai[1]), fmaxf(ai[2], ai[3]));
        float er[4], ei_[4], sre = 0.f, sie = 0.f;
#pragma unroll
        for (int P = 0; P < 4; P++) {
            er[P] = __expf(ar[P] - mr); sre += er[P];
            ei_[P] = __expf(ai[P] - mi); sie += ei_[P];
        }
        float rinv = 1.f / sre, iinv = 1.f / sie;
        float Cr = 0.f, Ci = 0.f;
#pragma unroll
        for (int P = 0; P < 4; P++) {
            float sr = er[P] * rinv, si = ei_[P] * iinv;
            float fr = sF[b * 4 + ks[P]].x, fi = sF[b * 4 + ks[P]].y;
            Cr += fr * sr - fi * si;
            Ci += fr * si + fi * sr;
        }
        // fold ifft2 norm 1/65536 and the 1/2 from Hermitian pair reconstruction
        d_Cp[e] = make_float2(Cr * (1.f / 131072.f), Ci * (1.f / 131072.f));
    }
}

// ---------------- KC: pair-packed row IFFT over 4 planes (radix-4) ----------------
__global__ void __launch_bounds__(128) kC_row() {
    __shared__ float2 bufA[2][256], bufB[2][256];
    __shared__ float2 tw[256];
    int q = blockIdx.x >> 7;      // 0..3 (plane: regions 2q, 2q+1)
    int rp = blockIdx.x & 127;    // row pair
    int t = threadIdx.x;          // 0..127

    for (int n = t; n < 256; n += 128) {
        float sn, cs;
        sincospif((float)n * (1.0f / 128.0f), &sn, &cs);
        tw[n] = make_float2(cs, sn);   // exp(+2*pi*i*n/256)
    }
    int row = t >> 6;
    int tt = t & 63;
    int i = rp * 2 + row;
    int m2q = 2 * q;
#pragma unroll
    for (int r = 0; r < 4; r++) {
        int col = tt + 64 * r;
        int id = region_id(i, col);
        bufA[row][col] = make_float2(id == m2q ? 1.f : 0.f, id == m2q + 1 ? 1.f : 0.f);
    }
    __syncthreads();

    float2 (*A)[256] = bufA;
    float2 (*Bf)[256] = bufB;
#pragma unroll
    for (int s = 0; s < 4; s++) {
        int m = 1 << (2 * s);
        int k = tt & (m - 1);
        int jm = tt - k;          // j*m
        float2 c0 = A[row][tt];
        float2 c1 = A[row][tt + 64];
        float2 c2 = A[row][tt + 128];
        float2 c3 = A[row][tt + 192];
        float2 t0 = make_float2(c0.x + c2.x, c0.y + c2.y);
        float2 t1 = make_float2(c0.x - c2.x, c0.y - c2.y);
        float2 t2 = make_float2(c1.x + c3.x, c1.y + c3.y);
        float2 t3 = make_float2(c1.x - c3.x, c1.y - c3.y);
        float2 z0 = make_float2(t0.x + t2.x, t0.y + t2.y);
        float2 z2 = make_float2(t0.x - t2.x, t0.y - t2.y);
        float2 z1 = make_float2(t1.x - t3.y, t1.y + t3.x);   // t1 + i*t3
        float2 z3 = make_float2(t1.x + t3.y, t1.y - t3.x);   // t1 - i*t3
        int lo = 4 * jm + k;
        Bf[row][lo] = z0;
        Bf[row][lo + m] = cmul(tw[jm], z1);
        Bf[row][lo + 2 * m] = cmul(tw[2 * jm], z2);
        Bf[row][lo + 3 * m] = cmul(tw[3 * jm], z3);
        __syncthreads();
        float2 (*tmp)[256] = A; A = Bf; Bf = tmp;
    }
    int base = q * 65536 + i * 256;
#pragma unroll
    for (int r = 0; r < 4; r++)
        d_Ym[base + tt + 64 * r] = A[row][tt + 64 * r];
}

// ---------------- KD: pair-packed column IFFT over 4 planes (radix-4) + kB block ----
__global__ void __launch_bounds__(256) kD_col(
        const float* __restrict__ w1r, const float* __restrict__ b1r,
        const float* __restrict__ w2r, const float* __restrict__ b2r,
        const float* __restrict__ w1i, const float* __restrict__ b1i,
        const float* __restrict__ w2i, const float* __restrict__ b2i) {
    if (blockIdx.x == 128) {
        kB_body(w1r, b1r, w2r, b2r, w1i, b1i, w2i, b2i);
        return;
    }
    __shared__ float2 tA[8 * 257];
    __shared__ float2 tB[8 * 257];
    __shared__ float2 tw[256];
    int q = blockIdx.x >> 5;     // 0..3
    int jt = blockIdx.x & 31;
    int j0 = jt * 8;
    int t = threadIdx.x;  // 256
    {
        float sn, cs;
        sincospif((float)t * (1.0f / 128.0f), &sn, &cs);
        tw[t] = make_float2(cs, sn);
    }
    int c = t & 7;
    int ib = t >> 3;
    int ybase = q * 65536;

#pragma unroll
    for (int r = 0; r < 8; r++) {
        int i = ib + r * 32;
        tA[c * 257 + i] = d_Ym[ybase + i * 256 + j0 + c];
    }
    __syncthreads();

    float2* A = tA;
    float2* Bf = tB;
#pragma unroll
    for (int s = 0; s < 4; s++) {
        int m = 1 << (2 * s);
#pragma unroll
        for (int u = 0; u < 2; u++) {
            int bf = t + u * 256;     // 0..511
            int col = bf >> 6;        // 0..7
            int tt = bf & 63;
            int k = tt & (m - 1);
            int jm = tt - k;
            float2 c0 = A[col * 257 + tt];
            float2 c1 = A[col * 257 + tt + 64];
            float2 c2 = A[col * 257 + tt + 128];
            float2 c3 = A[col * 257 + tt + 192];
            float2 t0 = make_float2(c0.x + c2.x, c0.y + c2.y);
            float2 t1 = make_float2(c0.x - c2.x, c0.y - c2.y);
            float2 t2 = make_float2(c1.x + c3.x, c1.y + c3.y);
            float2 t3 = make_float2(c1.x - c3.x, c1.y - c3.y);
            float2 z0 = make_float2(t0.x + t2.x, t0.y + t2.y);
            float2 z2 = make_float2(t0.x - t2.x, t0.y - t2.y);
            float2 z1 = make_float2(t1.x - t3.y, t1.y + t3.x);
            float2 z3 = make_float2(t1.x + t3.y, t1.y - t3.x);
            int lo = col * 257 + 4 * jm + k;
            Bf[lo] = z0;
            Bf[lo + m] = cmul(tw[jm], z1);
            Bf[lo + 2 * m] = cmul(tw[2 * jm], z2);
            Bf[lo + 3 * m] = cmul(tw[3 * jm], z3);
        }
        __syncthreads();
        float2* tmp = A; A = Bf; Bf = tmp;
    }
#pragma unroll
    for (int r = 0; r < 8; r++) {
        int i = ib + r * 32;
        d_W[ybase + i * 256 + j0 + c] = A[c * 257 + i];
    }
}

// ---------------- KE: q-outer combine over 8-bc chunk; pool fused; direct store --------
__global__ void __launch_bounds__(256, 4) kE_combine(const float* __restrict__ x,
                                                     float* __restrict__ out) {
    // sA/sB: [q][k][h] pre-duplicated (v,v) u64
    __shared__ unsigned long long sA[4 * 8 * 2];
    __shared__ unsigned long long sB[4 * 8 * 2];
    int i = blockIdx.x;          // 0..128
    int bc0 = blockIdx.y * 8;    // bc chunk base
    int j = threadIdx.x;         // 0..255
    if (threadIdx.x < 64) {
        int k = threadIdx.x >> 3, p = threadIdx.x & 7;
        float2 cp = d_Cp[(bc0 + k) * 8 + p];
        int q = p >> 1, h = p & 1;
        sA[(q * 8 + k) * 2 + h] = pk2(cp.x, cp.x);
        sB[(q * 8 + k) * 2 + h] = pk2(cp.y, cp.y);
    }
    __syncthreads();

    int im = (256 - i) & 255;
    int jmm = (256 - j) & 255;
    int pix = i * 256 + j;
    int mir = im * 256 + jmm;

    unsigned long long accA[8], accB[8];
#pragma unroll
    for (int k = 0; k < 8; k++) { accA[k] = 0ull; accB[k] = 0ull; }

#pragma unroll
    for (int q = 0; q < 4; q++) {
        float2 w = d_W[q * 65536 + pix];
        float2 wp = d_W[q * 65536 + mir];
        // U[2q] = (Wr+Wpr, Wi-Wpi); U[2q+1] = (Wi+Wpi, Wpr-Wr)
        unsigned long long U0 = pk2(w.x + wp.x, w.y - wp.y);
        unsigned long long U1 = pk2(w.y + wp.y, wp.x - w.x);
#pragma unroll
        for (int k = 0; k < 8; k++) {
            ulonglong2 a = *(const ulonglong2*)&sA[(q * 8 + k) * 2];
            ulonglong2 b = *(const ulonglong2*)&sB[(q * 8 + k) * 2];
            accA[k] = ffma2(a.x, U0, accA[k]);
            accA[k] = ffma2(a.y, U1, accA[k]);
            accB[k] = ffma2(b.x, U0, accB[k]);
            accB[k] = ffma2(b.y, U1, accB[k]);
        }
    }

    int xr0 = (2 * i) * 512 + 2 * j;
    int xr1 = xr0 + 512;
    int xm0 = (2 * im) * 512 + 2 * jmm;
    int xm1 = xm0 + 512;

#pragma unroll
    for (int k = 0; k < 8; k++) {
        float sa0, sa1, sb0, sb1;
        upk2(accA[k], sa0, sa1);
        upk2(accB[k], sb0, sb1);
        // pixel (i,j):   val = (sa0 - sb1) + i(sa1 + sb0)
        // pixel (-i,-j): val' = (sa0 + sb1) + i(sb0 - sa1)
        float ar = sa0 - sb1, ai = sa1 + sb0;
        float ar2 = sa0 + sb1, ai2 = sb0 - sa1;
        float r2a = fmaxf(fmaf(ar, ar, ai * ai), 1e-38f);
        float r2b = fmaxf(fmaf(ar2, ar2, ai2 * ai2), 1e-38f);
        float mag = r2a * __frsqrt_rn(r2a);
        float mag2 = r2b * __frsqrt_rn(r2b);

        int bc = bc0 + k;
        const float* xb = x + bc * 262144;
        float2 p0 = *(const float2*)(xb + xr0);
        float2 p1 = *(const float2*)(xb + xr1);
        float2 q0 = *(const float2*)(xb + xm0);
        float2 q1 = *(const float2*)(xb + xm1);
        unsigned ob = (unsigned)bc * 65536u;
        out[ob + pix] = mag + 0.25f * (p0.x + p0.y + p1.x + p1.y);
        out[ob + mir] = mag2 + 0.25f * (q0.x + q0.y + q1.x + q1.y);
    }
}

// ---------------- launch ----------------
extern "C" void kernel_launch(void* const* d_in, const int* in_sizes, int n_in,
                              void* d_out, int out_size) {
    const float* x   = (const float*)d_in[0];
    const float* w1r = (const float*)d_in[2];
    const float* b1r = (const float*)d_in[3];
    const float* w2r = (const float*)d_in[4];
    const float* b2r = (const float*)d_in[5];
    const float* w1i = (const float*)d_in[6];
    const float* b1i = (const float*)d_in[7];
    const float* w2i = (const float*)d_in[8];
    const float* b2i = (const float*)d_in[9];
    float* out = (float*)d_out;

    kA<<<16, 512>>>(x);
    kC_row<<<512, 128>>>();
    kD_col<<<129, 256>>>(w1r, b1r, w2r, b2r, w1i, b1i, w2i, b2i);
    kE_combine<<<dim3(129, 8), 256>>>(x, out);
}

// round 12
// speedup vs baseline: 2.6203x; 1.1425x over previous
#include <cuda_runtime.h>
#include <math.h>

// B=2, C=32, H=512, W=512, SCALE=2 -> Hs=Ws=256, S2=4
// The 4 patch magnitudes at pixel (i,j) are hypot(A_hb, B_wb) with
//   A0=256-i, A1=i+1, B0=256-j, B1=j+1   (patch p: hb=p&1, wb=p>>1)
// argsort order depends only on (i>>7, j>>7) and sign(i-j) / sign(i+j-255):
// only 8 permutations ("regions") occur. ifft2 linear => per (b,c):
// ifft2(X) = sum_r Cp[bc][r] * M_r over 8 region masks; masks real -> pack
// pairs into 4 complex IFFT planes; M(-u)=conj(M(u)) gives 2 pixels/thread.
// 3 launches: kAC (F-partials || mask row-FFTs) -> kD(+kB) -> kE.

// ---------------- scratch ----------------
__device__ float  d_Fpart[2 * 8 * 8];
__device__ float2 d_Cp[64 * 8];              // combined coef per (bc, region)
__device__ float2 d_Ym[4 * 256 * 256];       // row-IFFT intermediate (2.1MB)
__device__ float2 d_W[4 * 256 * 256];        // packed-pair 2D IFFT (2.1MB)

// ---------------- f32x2 helpers ----------------
__device__ __forceinline__ unsigned long long pk2(float lo, float hi) {
    unsigned long long r;
    asm("mov.b64 %0, {%1, %2};" : "=l"(r) : "f"(lo), "f"(hi));
    return r;
}
__device__ __forceinline__ void upk2(unsigned long long v, float& lo, float& hi) {
    asm("mov.b64 {%0, %1}, %2;" : "=f"(lo), "=f"(hi) : "l"(v));
}
__device__ __forceinline__ unsigned long long ffma2(unsigned long long a,
                                                    unsigned long long b,
                                                    unsigned long long c) {
    unsigned long long r;
    asm("fma.rn.f32x2 %0, %1, %2, %3;" : "=l"(r) : "l"(a), "l"(b), "l"(c));
    return r;
}
__device__ __forceinline__ float2 cmul(float2 w, float2 z) {
    return make_float2(w.x * z.x - w.y * z.y, w.x * z.y + w.y * z.x);
}

// region id 0..7 for pixel (i,j)
__device__ __forceinline__ int region_id(int i, int j) {
    int qi = i >> 7, qj = j >> 7;
    int u = (qi == qj) ? (i >= j) : (i + j <= 255);
    return (qi << 2) | (qj << 1) | u;
}

// ---------------- KAC: fused mask row-IFFTs (blocks 0..127) + F partials (128..143) ---
__global__ void __launch_bounds__(512) kAC(const float* __restrict__ x) {
    int blk = blockIdx.x;
    if (blk >= 128) {
        // --- kA part: column partial sums for F[b,t], channel 0 ---
        int bb = blk - 128;
        int b = bb >> 3, hb = bb & 7;
        int w = threadIdx.x;  // 512
        const float* xp = x + (size_t)b * 32 * 512 * 512 + (size_t)(hb * 64) * 512 + w;
        float s = 0.f;
#pragma unroll 8
        for (int h = 0; h < 64; h++) s += xp[(size_t)h * 512];

        float vals[8];
#pragma unroll
        for (int t = 0; t < 4; t++) {
            float ph = (float)(t * w) * (1.0f / 256.0f);
            float sn, cs;
            sincospif(ph, &sn, &cs);
            vals[2 * t] = s * cs;
            vals[2 * t + 1] = -s * sn;
        }
        unsigned lane = threadIdx.x & 31, wid = threadIdx.x >> 5;
#pragma unroll
        for (int v = 0; v < 8; v++)
#pragma unroll
            for (int off = 16; off; off >>= 1)
                vals[v] += __shfl_down_sync(0xffffffff, vals[v], off);
        __shared__ float wsum[16][8];
        if (lane == 0)
            for (int v = 0; v < 8; v++) wsum[wid][v] = vals[v];
        __syncthreads();
        if (threadIdx.x == 0) {
            for (int v = 0; v < 8; v++) {
                float a = 0.f;
                for (int k = 0; k < 16; k++) a += wsum[k][v];
                d_Fpart[(b * 8 + hb) * 8 + v] = a;
            }
        }
        return;
    }
    // --- kC part: pair-packed row IFFT, radix-4 Stockham, 8 rows/block ---
    __shared__ float2 bufA[8][256], bufB[8][256];
    __shared__ float2 tw[256];
    int q = blk >> 5;            // 0..3 (plane: regions 2q, 2q+1)
    int rg = blk & 31;           // row group (8 rows)
    int t = threadIdx.x;         // 0..511

    if (t < 256) {
        float sn, cs;
        sincospif((float)t * (1.0f / 128.0f), &sn, &cs);
        tw[t] = make_float2(cs, sn);   // exp(+2*pi*i*n/256)
    }
    int row = t >> 6;            // 0..7
    int tt = t & 63;
    int i = rg * 8 + row;
    int m2q = 2 * q;
#pragma unroll
    for (int r = 0; r < 4; r++) {
        int col = tt + 64 * r;
        int id = region_id(i, col);
        bufA[row][col] = make_float2(id == m2q ? 1.f : 0.f, id == m2q + 1 ? 1.f : 0.f);
    }
    __syncthreads();

    float2 (*A)[256] = bufA;
    float2 (*Bf)[256] = bufB;
#pragma unroll
    for (int s = 0; s < 4; s++) {
        int m = 1 << (2 * s);
        int k = tt & (m - 1);
        int jm = tt - k;          // j*m
        float2 c0 = A[row][tt];
        float2 c1 = A[row][tt + 64];
        float2 c2 = A[row][tt + 128];
        float2 c3 = A[row][tt + 192];
        float2 t0 = make_float2(c0.x + c2.x, c0.y + c2.y);
        float2 t1 = make_float2(c0.x - c2.x, c0.y - c2.y);
        float2 t2 = make_float2(c1.x + c3.x, c1.y + c3.y);
        float2 t3 = make_float2(c1.x - c3.x, c1.y - c3.y);
        float2 z0 = make_float2(t0.x + t2.x, t0.y + t2.y);
        float2 z2 = make_float2(t0.x - t2.x, t0.y - t2.y);
        float2 z1 = make_float2(t1.x - t3.y, t1.y + t3.x);   // t1 + i*t3
        float2 z3 = make_float2(t1.x + t3.y, t1.y - t3.x);   // t1 - i*t3
        int lo = 4 * jm + k;
        Bf[row][lo] = z0;
        Bf[row][lo + m] = cmul(tw[jm], z1);
        Bf[row][lo + 2 * m] = cmul(tw[2 * jm], z2);
        Bf[row][lo + 3 * m] = cmul(tw[3 * jm], z3);
        __syncthreads();
        float2 (*tmp)[256] = A; A = Bf; Bf = tmp;
    }
    int base = q * 65536 + i * 256;
#pragma unroll
    for (int r = 0; r < 4; r++)
        d_Ym[base + tt + 64 * r] = A[row][tt + 64 * r];
}

// ---------------- kB body (runs as the extra block of kD; 256 threads) ----------------
__device__ void kB_body(const float* __restrict__ w1r, const float* __restrict__ b1r,
                        const float* __restrict__ w2r, const float* __restrict__ b2r,
                        const float* __restrict__ w1i, const float* __restrict__ b1i,
                        const float* __restrict__ w2i, const float* __restrict__ b2i) {
    __shared__ float2 sF[8];
    __shared__ float sTR[1024], sTI[1024];
    int tid = threadIdx.x;  // 256
    if (tid < 8) {
        int b = tid >> 2, k = tid & 3;
        float re = 0.f, im = 0.f;
        for (int hb = 0; hb < 8; hb++) {
            re += d_Fpart[(b * 8 + hb) * 8 + 2 * k];
            im += d_Fpart[(b * 8 + hb) * 8 + 2 * k + 1];
        }
        sF[tid] = make_float2(re, im);
    }
    __syncthreads();

#pragma unroll
    for (int e0 = 0; e0 < 2048; e0 += 256) {
        int e = e0 + tid;
        int isI = e >> 10;
        int r = e & 1023;
        int b = r >> 9;
        int g = (r >> 4) & 31;
        int o = (r >> 2) & 3;
        int k = r & 3;
        const float* w1 = isI ? w1i : w1r;
        const float* b1 = isI ? b1i : b1r;
        const float* w2 = isI ? w2i : w2r;
        const float* b2 = isI ? b2i : b2r;
        float v = isI ? sF[b * 4 + k].y : sF[b * 4 + k].x;
        float h[4];
#pragma unroll
        for (int ii = 0; ii < 4; ii++) {
            const float* wrow = w1 + (g * 4 + ii) * 4;
            float ws = wrow[0] + wrow[1] + wrow[2] + wrow[3];
            float y = v * ws + b1[g * 4 + ii];
            h[ii] = y > 0.f ? y : 0.1f * y;
        }
        float out = b2[g * 4 + o];
#pragma unroll
        for (int ii = 0; ii < 4; ii++) out += w2[(g * 4 + o) * 4 + ii] * h[ii];
        (isI ? sTI : sTR)[r] = out;
    }
    __syncthreads();

    // 512 outputs: e = bc*8 + region
    for (int e = tid; e < 512; e += 256) {
        int bc = e >> 3;
        int rg = e & 7;
        int b = bc >> 5, Cc = bc & 31;
        // decode region -> descending patch order ks[0..3]
        int qi = (rg >> 2) & 1, qj = (rg >> 1) & 1, u = rg & 1;
        int first = (qj << 1) | qi;
        int last = first ^ 3;
        int mids0 = (qi == qj) ? (u ? 1 : 2) : (u ? 0 : 3);
        int mids1 = mids0 ^ 3;
        int ks[4] = { first, mids0, mids1, last };

        float ar[4], ai[4];
#pragma unroll
        for (int P = 0; P < 4; P++) {
            int g = 8 * P + (Cc >> 2), o = Cc & 3;
            int idx = ((b * 32 + g) * 4 + o) * 4 + ks[P];
            ar[P] = sTR[idx & 1023];
            ai[P] = sTI[idx & 1023];
        }
        float mr = fmaxf(fmaxf(ar[0], ar[1]), fmaxf(ar[2], ar[3]));
        float mi = fmaxf(fmaxf(ai[0], ai[1]), fmaxf(ai[2], ai[3]));
        float er[4], ei_[4], sre = 0.f, sie = 0.f;
#pragma unroll
        for (int P = 0; P < 4; P++) {
            er[P] = __expf(ar[P] - mr); sre += er[P];
            ei_[P] = __expf(ai[P] - mi); sie += ei_[P];
        }
        float rinv = 1.f / sre, iinv = 1.f / sie;
        float Cr = 0.f, Ci = 0.f;
#pragma unroll
        for (int P = 0; P < 4; P++) {
            float sr = er[P] * rinv, si = ei_[P] * iinv;
            float fr = sF[b * 4 + ks[P]].x, fi = sF[b * 4 + ks[P]].y;
            Cr += fr * sr - fi * si;
            Ci += fr * si + fi * sr;
        }
        // fold ifft2 norm 1/65536 and the 1/2 from Hermitian pair reconstruction
        d_Cp[e] = make_float2(Cr * (1.f / 131072.f), Ci * (1.f / 131072.f));
    }
}

// ---------------- KD: pair-packed column IFFT over 4 planes (radix-4) + kB block ----
__global__ void __launch_bounds__(256) kD_col(
        const float* __restrict__ w1r, const float* __restrict__ b1r,
        const float* __restrict__ w2r, const float* __restrict__ b2r,
        const float* __restrict__ w1i, const float* __restrict__ b1i,
        const float* __restrict__ w2i, const float* __restrict__ b2i) {
    if (blockIdx.x == 128) {
        kB_body(w1r, b1r, w2r, b2r, w1i, b1i, w2i, b2i);
        return;
    }
    __shared__ float2 tA[8 * 257];
    __shared__ float2 tB[8 * 257];
    __shared__ float2 tw[256];
    int q = blockIdx.x >> 5;     // 0..3
    int jt = blockIdx.x & 31;
    int j0 = jt * 8;
    int t = threadIdx.x;  // 256
    {
        float sn, cs;
        sincospif((float)t * (1.0f / 128.0f), &sn, &cs);
        tw[t] = make_float2(cs, sn);
    }
    int c = t & 7;
    int ib = t >> 3;
    int ybase = q * 65536;

#pragma unroll
    for (int r = 0; r < 8; r++) {
        int i = ib + r * 32;
        tA[c * 257 + i] = d_Ym[ybase + i * 256 + j0 + c];
    }
    __syncthreads();

    float2* A = tA;
    float2* Bf = tB;
#pragma unroll
    for (int s = 0; s < 4; s++) {
        int m = 1 << (2 * s);
#pragma unroll
        for (int u = 0; u < 2; u++) {
            int bf = t + u * 256;     // 0..511
            int col = bf >> 6;        // 0..7
            int tt = bf & 63;
            int k = tt & (m - 1);
            int jm = tt - k;
            float2 c0 = A[col * 257 + tt];
            float2 c1 = A[col * 257 + tt + 64];
            float2 c2 = A[col * 257 + tt + 128];
            float2 c3 = A[col * 257 + tt + 192];
            float2 t0 = make_float2(c0.x + c2.x, c0.y + c2.y);
            float2 t1 = make_float2(c0.x - c2.x, c0.y - c2.y);
            float2 t2 = make_float2(c1.x + c3.x, c1.y + c3.y);
            float2 t3 = make_float2(c1.x - c3.x, c1.y - c3.y);
            float2 z0 = make_float2(t0.x + t2.x, t0.y + t2.y);
            float2 z2 = make_float2(t0.x - t2.x, t0.y - t2.y);
            float2 z1 = make_float2(t1.x - t3.y, t1.y + t3.x);
            float2 z3 = make_float2(t1.x + t3.y, t1.y - t3.x);
            int lo = col * 257 + 4 * jm + k;
            Bf[lo] = z0;
            Bf[lo + m] = cmul(tw[jm], z1);
            Bf[lo + 2 * m] = cmul(tw[2 * jm], z2);
            Bf[lo + 3 * m] = cmul(tw[3 * jm], z3);
        }
        __syncthreads();
        float2* tmp = A; A = Bf; Bf = tmp;
    }
#pragma unroll
    for (int r = 0; r < 8; r++) {
        int i = ib + r * 32;
        d_W[ybase + i * 256 + j0 + c] = A[c * 257 + i];
    }
}

// ---------------- KE: q-outer combine over 4-bc chunk; pool fused; direct store --------
__global__ void __launch_bounds__(256, 4) kE_combine(const float* __restrict__ x,
                                                     float* __restrict__ out) {
    // sA/sB: [q][k][h] pre-duplicated (v,v) u64
    __shared__ unsigned long long sA[4 * 4 * 2];
    __shared__ unsigned long long sB[4 * 4 * 2];
    int i = blockIdx.x;          // 0..128
    int bc0 = blockIdx.y * 4;    // bc chunk base
    int j = threadIdx.x;         // 0..255
    if (threadIdx.x < 32) {
        int k = threadIdx.x >> 3, p = threadIdx.x & 7;
        float2 cp = d_Cp[(bc0 + k) * 8 + p];
        int q = p >> 1, h = p & 1;
        sA[(q * 4 + k) * 2 + h] = pk2(cp.x, cp.x);
        sB[(q * 4 + k) * 2 + h] = pk2(cp.y, cp.y);
    }
    __syncthreads();

    int im = (256 - i) & 255;
    int jmm = (256 - j) & 255;
    int pix = i * 256 + j;
    int mir = im * 256 + jmm;

    unsigned long long accA[4], accB[4];
#pragma unroll
    for (int k = 0; k < 4; k++) { accA[k] = 0ull; accB[k] = 0ull; }

#pragma unroll
    for (int q = 0; q < 4; q++) {
        float2 w = d_W[q * 65536 + pix];
        float2 wp = d_W[q * 65536 + mir];
        // U[2q] = (Wr+Wpr, Wi-Wpi); U[2q+1] = (Wi+Wpi, Wpr-Wr)
        unsigned long long U0 = pk2(w.x + wp.x, w.y - wp.y);
        unsigned long long U1 = pk2(w.y + wp.y, wp.x - w.x);
#pragma unroll
        for (int k = 0; k < 4; k++) {
            ulonglong2 a = *(const ulonglong2*)&sA[(q * 4 + k) * 2];
            ulonglong2 b = *(const ulonglong2*)&sB[(q * 4 + k) * 2];
            accA[k] = ffma2(a.x, U0, accA[k]);
            accA[k] = ffma2(a.y, U1, accA[k]);
            accB[k] = ffma2(b.x, U0, accB[k]);
            accB[k] = ffma2(b.y, U1, accB[k]);
        }
    }

    int xr0 = (2 * i) * 512 + 2 * j;
    int xr1 = xr0 + 512;
    int xm0 = (2 * im) * 512 + 2 * jmm;
    int xm1 = xm0 + 512;

#pragma unroll
    for (int k = 0; k < 4; k++) {
        float sa0, sa1, sb0, sb1;
        upk2(accA[k], sa0, sa1);
        upk2(accB[k], sb0, sb1);
        // pixel (i,j):   val = (sa0 - sb1) + i(sa1 + sb0)
        // pixel (-i,-j): val' = (sa0 + sb1) + i(sb0 - sa1)
        float ar = sa0 - sb1, ai = sa1 + sb0;
        float ar2 = sa0 + sb1, ai2 = sb0 - sa1;
        float r2a = fmaxf(fmaf(ar, ar, ai * ai), 1e-38f);
        float r2b = fmaxf(fmaf(ar2, ar2, ai2 * ai2), 1e-38f);
        float mag = r2a * __frsqrt_rn(r2a);
        float mag2 = r2b * __frsqrt_rn(r2b);

        int bc = bc0 + k;
        const float* xb = x + bc * 262144;
        float2 p0 = *(const float2*)(xb + xr0);
        float2 p1 = *(const float2*)(xb + xr1);
        float2 q0 = *(const float2*)(xb + xm0);
        float2 q1 = *(const float2*)(xb + xm1);
        unsigned ob = (unsigned)bc * 65536u;
        out[ob + pix] = mag + 0.25f * (p0.x + p0.y + p1.x + p1.y);
        out[ob + mir] = mag2 + 0.25f * (q0.x + q0.y + q1.x + q1.y);
    }
}

// ---------------- launch ----------------
extern "C" void kernel_launch(void* const* d_in, const int* in_sizes, int n_in,
                              void* d_out, int out_size) {
    const float* x   = (const float*)d_in[0];
    const float* w1r = (const float*)d_in[2];
    const float* b1r = (const float*)d_in[3];
    const float* w2r = (const float*)d_in[4];
    const float* b2r = (const float*)d_in[5];
    const float* w1i = (const float*)d_in[6];
    const float* b1i = (const float*)d_in[7];
    const float* w2i = (const float*)d_in[8];
    const float* b2i = (const float*)d_in[9];
    float* out = (float*)d_out;

    kAC<<<144, 512>>>(x);
    kD_col<<<129, 256>>>(w1r, b1r, w2r, b2r, w1i, b1i, w2i, b2i);
    kE_combine<<<dim3(129, 16), 256>>>(x, out);
}

// round 14
// speedup vs baseline: 2.7553x; 1.0515x over previous
#include <cuda_runtime.h>
#include <math.h>

// B=2, C=32, H=512, W=512, SCALE=2 -> Hs=Ws=256, S2=4
// The 4 patch magnitudes at pixel (i,j) are hypot(A_hb, B_wb) with
//   A0=256-i, A1=i+1, B0=256-j, B1=j+1   (patch p: hb=p&1, wb=p>>1)
// argsort order depends only on (i>>7, j>>7) and sign(i-j) / sign(i+j-255):
// only 8 permutations ("regions") occur. ifft2 linear => per (b,c):
// ifft2(X) = sum_r Cp[bc][r] * M_r over 8 region masks; masks real -> pack
// pairs into 4 complex IFFT planes; M(-u)=conj(M(u)) gives 2 pixels/thread.
// 3 launches: kAC (F-partials || mask row-FFTs, load-balanced) -> kD(+kB) -> kE.

// ---------------- scratch ----------------
__device__ float  d_Fpart[2 * 32 * 8];       // [b][hb(32 x 16-row slabs)][t*2+reim]
__device__ float2 d_Cp[64 * 8];              // combined coef per (bc, region)
__device__ float2 d_Ym[4 * 256 * 256];       // row-IFFT intermediate (2.1MB)
__device__ float2 d_W[4 * 256 * 256];        // packed-pair 2D IFFT (2.1MB)

// ---------------- f32x2 helpers ----------------
__device__ __forceinline__ unsigned long long pk2(float lo, float hi) {
    unsigned long long r;
    asm("mov.b64 %0, {%1, %2};" : "=l"(r) : "f"(lo), "f"(hi));
    return r;
}
__device__ __forceinline__ void upk2(unsigned long long v, float& lo, float& hi) {
    asm("mov.b64 {%0, %1}, %2;" : "=f"(lo), "=f"(hi) : "l"(v));
}
__device__ __forceinline__ unsigned long long ffma2(unsigned long long a,
                                                    unsigned long long b,
                                                    unsigned long long c) {
    unsigned long long r;
    asm("fma.rn.f32x2 %0, %1, %2, %3;" : "=l"(r) : "l"(a), "l"(b), "l"(c));
    return r;
}
__device__ __forceinline__ float2 cmul(float2 w, float2 z) {
    return make_float2(w.x * z.x - w.y * z.y, w.x * z.y + w.y * z.x);
}

// region id 0..7 for pixel (i,j)
__device__ __forceinline__ int region_id(int i, int j) {
    int qi = i >> 7, qj = j >> 7;
    int u = (qi == qj) ? (i >= j) : (i + j <= 255);
    return (qi << 2) | (qj << 1) | u;
}

// ---------------- KAC: mask row-IFFTs (blocks 0..127) + F partials (128..191) ---------
__global__ void __launch_bounds__(512) kAC(const float* __restrict__ x) {
    int blk = blockIdx.x;
    if (blk >= 128) {
        // --- kA part: column partial sums for F[b,t], channel 0, 16 rows/block ---
        int bb = blk - 128;          // 0..63
        int b = bb >> 5, hb = bb & 31;
        int w = threadIdx.x;  // 512
        const float* xp = x + (size_t)b * 32 * 512 * 512 + (size_t)(hb * 16) * 512 + w;
        float s = 0.f;
#pragma unroll
        for (int h = 0; h < 16; h++) s += xp[(size_t)h * 512];

        float vals[8];
#pragma unroll
        for (int t = 0; t < 4; t++) {
            float ph = (float)(t * w) * (1.0f / 256.0f);
            float sn, cs;
            sincospif(ph, &sn, &cs);
            vals[2 * t] = s * cs;
            vals[2 * t + 1] = -s * sn;
        }
        unsigned lane = threadIdx.x & 31, wid = threadIdx.x >> 5;
#pragma unroll
        for (int v = 0; v < 8; v++)
#pragma unroll
            for (int off = 16; off; off >>= 1)
                vals[v] += __shfl_down_sync(0xffffffff, vals[v], off);
        __shared__ float wsum[16][8];
        if (lane == 0)
            for (int v = 0; v < 8; v++) wsum[wid][v] = vals[v];
        __syncthreads();
        if (threadIdx.x == 0) {
            for (int v = 0; v < 8; v++) {
                float a = 0.f;
                for (int k = 0; k < 16; k++) a += wsum[k][v];
                d_Fpart[(b * 32 + hb) * 8 + v] = a;
            }
        }
        return;
    }
    // --- kC part: pair-packed row IFFT, radix-4 Stockham, 8 rows/block ---
    __shared__ float2 bufA[8][256], bufB[8][256];
    __shared__ float2 tw[256];
    int q = blk >> 5;            // 0..3 (plane: regions 2q, 2q+1)
    int rg = blk & 31;           // row group (8 rows)
    int t = threadIdx.x;         // 0..511

    if (t < 256) {
        float sn, cs;
        sincospif((float)t * (1.0f / 128.0f), &sn, &cs);
        tw[t] = make_float2(cs, sn);   // exp(+2*pi*i*n/256)
    }
    int row = t >> 6;            // 0..7
    int tt = t & 63;
    int i = rg * 8 + row;
    int m2q = 2 * q;
#pragma unroll
    for (int r = 0; r < 4; r++) {
        int col = tt + 64 * r;
        int id = region_id(i, col);
        bufA[row][col] = make_float2(id == m2q ? 1.f : 0.f, id == m2q + 1 ? 1.f : 0.f);
    }
    __syncthreads();

    float2 (*A)[256] = bufA;
    float2 (*Bf)[256] = bufB;
#pragma unroll
    for (int s = 0; s < 4; s++) {
        int m = 1 << (2 * s);
        int k = tt & (m - 1);
        int jm = tt - k;          // j*m
        float2 c0 = A[row][tt];
        float2 c1 = A[row][tt + 64];
        float2 c2 = A[row][tt + 128];
        float2 c3 = A[row][tt + 192];
        float2 t0 = make_float2(c0.x + c2.x, c0.y + c2.y);
        float2 t1 = make_float2(c0.x - c2.x, c0.y - c2.y);
        float2 t2 = make_float2(c1.x + c3.x, c1.y + c3.y);
        float2 t3 = make_float2(c1.x - c3.x, c1.y - c3.y);
        float2 z0 = make_float2(t0.x + t2.x, t0.y + t2.y);
        float2 z2 = make_float2(t0.x - t2.x, t0.y - t2.y);
        float2 z1 = make_float2(t1.x - t3.y, t1.y + t3.x);   // t1 + i*t3
        float2 z3 = make_float2(t1.x + t3.y, t1.y - t3.x);   // t1 - i*t3
        int lo = 4 * jm + k;
        Bf[row][lo] = z0;
        Bf[row][lo + m] = cmul(tw[jm], z1);
        Bf[row][lo + 2 * m] = cmul(tw[2 * jm], z2);
        Bf[row][lo + 3 * m] = cmul(tw[3 * jm], z3);
        __syncthreads();
        float2 (*tmp)[256] = A; A = Bf; Bf = tmp;
    }
    int base = q * 65536 + i * 256;
#pragma unroll
    for (int r = 0; r < 4; r++)
        d_Ym[base + tt + 64 * r] = A[row][tt + 64 * r];
}

// ---------------- kB body (runs as the extra block of kD; 256 threads) ----------------
__device__ void kB_body(const float* __restrict__ w1r, const float* __restrict__ b1r,
                        const float* __restrict__ w2r, const float* __restrict__ b2r,
                        const float* __restrict__ w1i, const float* __restrict__ b1i,
                        const float* __restrict__ w2i, const float* __restrict__ b2i) {
    __shared__ float2 sF[8];
    __shared__ float sTR[1024], sTI[1024];
    int tid = threadIdx.x;  // 256
    if (tid < 8) {
        int b = tid >> 2, k = tid & 3;
        float re = 0.f, im = 0.f;
        for (int hb = 0; hb < 32; hb++) {
            re += d_Fpart[(b * 32 + hb) * 8 + 2 * k];
            im += d_Fpart[(b * 32 + hb) * 8 + 2 * k + 1];
        }
        sF[tid] = make_float2(re, im);
    }
    __syncthreads();

#pragma unroll
    for (int e0 = 0; e0 < 2048; e0 += 256) {
        int e = e0 + tid;
        int isI = e >> 10;
        int r = e & 1023;
        int b = r >> 9;
        int g = (r >> 4) & 31;
        int o = (r >> 2) & 3;
        int k = r & 3;
        const float* w1 = isI ? w1i : w1r;
        const float* b1 = isI ? b1i : b1r;
        const float* w2 = isI ? w2i : w2r;
        const float* b2 = isI ? b2i : b2r;
        float v = isI ? sF[b * 4 + k].y : sF[b * 4 + k].x;
        float h[4];
#pragma unroll
        for (int ii = 0; ii < 4; ii++) {
            const float* wrow = w1 + (g * 4 + ii) * 4;
            float ws = wrow[0] + wrow[1] + wrow[2] + wrow[3];
            float y = v * ws + b1[g * 4 + ii];
            h[ii] = y > 0.f ? y : 0.1f * y;
        }
        float out = b2[g * 4 + o];
#pragma unroll
        for (int ii = 0; ii < 4; ii++) out += w2[(g * 4 + o) * 4 + ii] * h[ii];
        (isI ? sTI : sTR)[r] = out;
    }
    __syncthreads();

    // 512 outputs: e = bc*8 + region
    for (int e = tid; e < 512; e += 256) {
        int bc = e >> 3;
        int rg = e & 7;
        int b = bc >> 5, Cc = bc & 31;
        // decode region -> descending patch order ks[0..3]
        int qi = (rg >> 2) & 1, qj = (rg >> 1) & 1, u = rg & 1;
        int first = (qj << 1) | qi;
        int last = first ^ 3;
        int mids0 = (qi == qj) ? (u ? 1 : 2) : (u ? 0 : 3);
        int mids1 = mids0 ^ 3;
        int ks[4] = { first, mids0, mids1, last };

        float ar[4], ai[4];
#pragma unroll
        for (int P = 0; P < 4; P++) {
            int g = 8 * P + (Cc >> 2), o = Cc & 3;
            int idx = ((b * 32 + g) * 4 + o) * 4 + ks[P];
            ar[P] = sTR[idx & 1023];
            ai[P] = sTI[idx & 1023];
        }
        float mr = fmaxf(fmaxf(ar[0], ar[1]), fmaxf(ar[2], ar[3]));
        float mi = fmaxf(fmaxf(ai[0], ai[1]), fmaxf(ai[2], ai[3]));
        float er[4], ei_[4], sre = 0.f, sie = 0.f;
#pragma unroll
        for (int P = 0; P < 4; P++) {
            er[P] = __expf(ar[P] - mr); sre += er[P];
            ei_[P] = __expf(ai[P] - mi); sie += ei_[P];
        }
        float rinv = 1.f / sre, iinv = 1.f / sie;
        float Cr = 0.f, Ci = 0.f;
#pragma unroll
        for (int P = 0; P < 4; P++) {
            float sr = er[P] * rinv, si = ei_[P] * iinv;
            float fr = sF[b * 4 + ks[P]].x, fi = sF[b * 4 + ks[P]].y;
            Cr += fr * sr - fi * si;
            Ci += fr * si + fi * sr;
        }
        // fold ifft2 norm 1/65536 and the 1/2 from Hermitian pair reconstruction
        d_Cp[e] = make_float2(Cr * (1.f / 131072.f), Ci * (1.f / 131072.f));
    }
}

// ---------------- KD: pair-packed column IFFT over 4 planes (radix-4) + kB block ----
__global__ void __launch_bounds__(256) kD_col(
        const float* __restrict__ w1r, const float* __restrict__ b1r,
        const float* __restrict__ w2r, const float* __restrict__ b2r,
        const float* __restrict__ w1i, const float* __restrict__ b1i,
        const float* __restrict__ w2i, const float* __restrict__ b2i) {
    if (blockIdx.x == 128) {
        kB_body(w1r, b1r, w2r, b2r, w1i, b1i, w2i, b2i);
        return;
    }
    __shared__ float2 tA[8 * 257];
    __shared__ float2 tB[8 * 257];
    __shared__ float2 tw[256];
    int q = blockIdx.x >> 5;     // 0..3
    int jt = blockIdx.x & 31;
    int j0 = jt * 8;
    int t = threadIdx.x;  // 256
    {
        float sn, cs;
        sincospif((float)t * (1.0f / 128.0f), &sn, &cs);
        tw[t] = make_float2(cs, sn);
    }
    int c = t & 7;
    int ib = t >> 3;
    int ybase = q * 65536;

#pragma unroll
    for (int r = 0; r < 8; r++) {
        int i = ib + r * 32;
        tA[c * 257 + i] = d_Ym[ybase + i * 256 + j0 + c];
    }
    __syncthreads();

    float2* A = tA;
    float2* Bf = tB;
#pragma unroll
    for (int s = 0; s < 4; s++) {
        int m = 1 << (2 * s);
#pragma unroll
        for (int u = 0; u < 2; u++) {
            int bf = t + u * 256;     // 0..511
            int col = bf >> 6;        // 0..7
            int tt = bf & 63;
            int k = tt & (m - 1);
            int jm = tt - k;
            float2 c0 = A[col * 257 + tt];
            float2 c1 = A[col * 257 + tt + 64];
            float2 c2 = A[col * 257 + tt + 128];
            float2 c3 = A[col * 257 + tt + 192];
            float2 t0 = make_float2(c0.x + c2.x, c0.y + c2.y);
            float2 t1 = make_float2(c0.x - c2.x, c0.y - c2.y);
            float2 t2 = make_float2(c1.x + c3.x, c1.y + c3.y);
            float2 t3 = make_float2(c1.x - c3.x, c1.y - c3.y);
            float2 z0 = make_float2(t0.x + t2.x, t0.y + t2.y);
            float2 z2 = make_float2(t0.x - t2.x, t0.y - t2.y);
            float2 z1 = make_float2(t1.x - t3.y, t1.y + t3.x);
            float2 z3 = make_float2(t1.x + t3.y, t1.y - t3.x);
            int lo = col * 257 + 4 * jm + k;
            Bf[lo] = z0;
            Bf[lo + m] = cmul(tw[jm], z1);
            Bf[lo + 2 * m] = cmul(tw[2 * jm], z2);
            Bf[lo + 3 * m] = cmul(tw[3 * jm], z3);
        }
        __syncthreads();
        float2* tmp = A; A = Bf; Bf = tmp;
    }
#pragma unroll
    for (int r = 0; r < 8; r++) {
        int i = ib + r * 32;
        d_W[ybase + i * 256 + j0 + c] = A[c * 257 + i];
    }
}

// ---------------- KE: q-outer combine over 4-bc chunk; pool fused; direct store --------
__global__ void __launch_bounds__(256, 4) kE_combine(const float* __restrict__ x,
                                                     float* __restrict__ out) {
    // sA/sB: [q][k][h] pre-duplicated (v,v) u64
    __shared__ unsigned long long sA[4 * 4 * 2];
    __shared__ unsigned long long sB[4 * 4 * 2];
    int i = blockIdx.x;          // 0..128
    int bc0 = blockIdx.y * 4;    // bc chunk base
    int j = threadIdx.x;         // 0..255
    if (threadIdx.x < 32) {
        int k = threadIdx.x >> 3, p = threadIdx.x & 7;
        float2 cp = d_Cp[(bc0 + k) * 8 + p];
        int q = p >> 1, h = p & 1;
        sA[(q * 4 + k) * 2 + h] = pk2(cp.x, cp.x);
        sB[(q * 4 + k) * 2 + h] = pk2(cp.y, cp.y);
    }
    __syncthreads();

    int im = (256 - i) & 255;
    int jmm = (256 - j) & 255;
    int pix = i * 256 + j;
    int mir = im * 256 + jmm;

    unsigned long long accA[4], accB[4];
#pragma unroll
    for (int k = 0; k < 4; k++) { accA[k] = 0ull; accB[k] = 0ull; }

#pragma unroll
    for (int q = 0; q < 4; q++) {
        float2 w = d_W[q * 65536 + pix];
        float2 wp = d_W[q * 65536 + mir];
        // U[2q] = (Wr+Wpr, Wi-Wpi); U[2q+1] = (Wi+Wpi, Wpr-Wr)
        unsigned long long U0 = pk2(w.x + wp.x, w.y - wp.y);
        unsigned long long U1 = pk2(w.y + wp.y, wp.x - w.x);
#pragma unroll
        for (int k = 0; k < 4; k++) {
            ulonglong2 a = *(const ulonglong2*)&sA[(q * 4 + k) * 2];
            ulonglong2 b = *(const ulonglong2*)&sB[(q * 4 + k) * 2];
            accA[k] = ffma2(a.x, U0, accA[k]);
            accA[k] = ffma2(a.y, U1, accA[k]);
            accB[k] = ffma2(b.x, U0, accB[k]);
            accB[k] = ffma2(b.y, U1, accB[k]);
        }
    }

    int xr0 = (2 * i) * 512 + 2 * j;
    int xr1 = xr0 + 512;
    int xm0 = (2 * im) * 512 + 2 * jmm;
    int xm1 = xm0 + 512;

#pragma unroll
    for (int k = 0; k < 4; k++) {
        float sa0, sa1, sb0, sb1;
        upk2(accA[k], sa0, sa1);
        upk2(accB[k], sb0, sb1);
        // pixel (i,j):   val = (sa0 - sb1) + i(sa1 + sb0)
        // pixel (-i,-j): val' = (sa0 + sb1) + i(sb0 - sa1)
        float ar = sa0 - sb1, ai = sa1 + sb0;
        float ar2 = sa0 + sb1, ai2 = sb0 - sa1;
        float r2a = fmaxf(fmaf(ar, ar, ai * ai), 1e-38f);
        float r2b = fmaxf(fmaf(ar2, ar2, ai2 * ai2), 1e-38f);
        float mag = r2a * __frsqrt_rn(r2a);
        float mag2 = r2b * __frsqrt_rn(r2b);

        int bc = bc0 + k;
        const float* xb = x + bc * 262144;
        float2 p0 = *(const float2*)(xb + xr0);
        float2 p1 = *(const float2*)(xb + xr1);
        float2 q0 = *(const float2*)(xb + xm0);
        float2 q1 = *(const float2*)(xb + xm1);
        unsigned ob = (unsigned)bc * 65536u;
        out[ob + pix] = mag + 0.25f * (p0.x + p0.y + p1.x + p1.y);
        out[ob + mir] = mag2 + 0.25f * (q0.x + q0.y + q1.x + q1.y);
    }
}

// ---------------- launch ----------------
extern "C" void kernel_launch(void* const* d_in, const int* in_sizes, int n_in,
                              void* d_out, int out_size) {
    const float* x   = (const float*)d_in[0];
    const float* w1r = (const float*)d_in[2];
    const float* b1r = (const float*)d_in[3];
    const float* w2r = (const float*)d_in[4];
    const float* b2r = (const float*)d_in[5];
    const float* w1i = (const float*)d_in[6];
    const float* b1i = (const float*)d_in[7];
    const float* w2i = (const float*)d_in[8];
    const float* b2i = (const float*)d_in[9];
    float* out = (float*)d_out;

    kAC<<<192, 512>>>(x);
    kD_col<<<129, 256>>>(w1r, b1r, w2r, b2r, w1i, b1i, w2i, b2i);
    kE_combine<<<dim3(129, 16), 256>>>(x, out);
}